// round 12
// baseline (speedup 1.0000x reference)
#include <cuda_runtime.h>
#include <cstdint>

constexpr int LDIM = 384;
constexpr int NHW  = 147456;   // 384*384
constexpr int CH   = 64;
constexpr int ND1  = 788;
constexpr int ND2  = 210;
#define EPSV 1e-5f

// ---------------- device scratch (static, no allocations) ----------------
__device__ float g_bufT[CH*NHW];
__device__ float g_bufU[CH*NHW];
__device__ float g_bufX[CH*NHW];
__device__ float g_bufV[CH*NHW];   // residual ping-pong partner of bufX
__device__ float g_rs1[ND1];
__device__ float g_rs2[ND2];
__device__ float g_W1af[CH*ND1];
__device__ float g_W1bf[CH*ND1];
__device__ float g_W2f[CH*ND2];
__device__ float g_row[CH*LDIM];
__device__ float g_col[CH*LDIM];
__device__ float g_a1[CH], g_c1[CH];
__device__ float g_accS[ND2], g_accQ[ND2];
// 12 per-channel stat sets (sum / sumsq), each written once per run
__device__ float g_sS[12*64];
__device__ float g_sQ[12*64];
// conv weights as B-fragment words: [lk][half][tap][cipair 16][72 (64 used)]
__device__ uint32_t g_wBh[10*2*9*16*72];
__device__ uint32_t g_wBl[10*2*9*16*72];

__device__ __forceinline__ float lrelu(float v){ return fmaxf(v, 0.01f*v); }

__device__ __forceinline__ float wsum(float v){
  #pragma unroll
  for(int o=16;o>0;o>>=1) v += __shfl_down_sync(0xffffffffu, v, o);
  return v;
}

__device__ __forceinline__ void bf16split2(float v0, float v1, uint32_t& hp, uint32_t& lp){
  asm("cvt.rn.bf16x2.f32 %0, %1, %2;" : "=r"(hp) : "f"(v1), "f"(v0));
  float h0 = __uint_as_float(hp<<16);
  float h1 = __uint_as_float(hp & 0xffff0000u);
  float l0 = v0 - h0, l1 = v1 - h1;
  asm("cvt.rn.bf16x2.f32 %0, %1, %2;" : "=r"(lp) : "f"(l1), "f"(l0));
}

#define MMA16816(d, a, b0, b1) \
  asm volatile("mma.sync.aligned.m16n8k16.row.col.f32.bf16.bf16.f32 " \
    "{%0,%1,%2,%3}, {%4,%5,%6,%7}, {%8,%9}, {%0,%1,%2,%3};" \
    : "+f"((d)[0]),"+f"((d)[1]),"+f"((d)[2]),"+f"((d)[3]) \
    : "r"((a)[0]),"r"((a)[1]),"r"((a)[2]),"r"((a)[3]), "r"(b0),"r"(b1))

#define REDADD(p, v) asm volatile("red.global.add.f32 [%0], %1;" :: "l"(p), "f"(v) : "memory")

__device__ __forceinline__ void aff_from_stats(const float* sS, const float* sQ,
                                               const float* gm, const float* bt,
                                               int c, float& a, float& cc){
  float mu = sS[c]*(1.f/(float)NHW);
  float var = sQ[c]*(1.f/(float)NHW) - mu*mu;
  a = gm[c]*rsqrtf(var+EPSV);
  cc = bt[c]-mu*a;
}

// ---------------- small kernels ----------------
__global__ void k_zero(){
  int t = threadIdx.x;
  if(t < 768){ g_sS[t]=0.f; g_sQ[t]=0.f; }
  if(t < ND2){ g_accS[t]=0.f; g_accQ[t]=0.f; }
}

// merged front kernel: blocks [0,788) stats1d, [788,1628) stats2, [1628,2348) prepB
__global__ void k_front(const float* __restrict__ x1, const float* __restrict__ x2,
                        const float* __restrict__ rw){
  int b = blockIdx.x;
  int tid = threadIdx.x;
  if(b < 788){
    const float* p = x1 + b*LDIM;
    float s=0.f,q=0.f;
    for(int i=tid;i<LDIM;i+=256){ float v=p[i]; s+=v; q+=v*v; }
    __shared__ float ss[8], sq[8];
    s = wsum(s); q = wsum(q);
    int w = tid>>5, ln = tid&31;
    if(ln==0){ ss[w]=s; sq[w]=q; }
    __syncthreads();
    if(tid==0){
      float S=0.f,Q=0.f;
      #pragma unroll
      for(int i=0;i<8;i++){S+=ss[i];Q+=sq[i];}
      float mu=S/(float)LDIM; float var=Q/(float)LDIM-mu*mu;
      g_rs1[b]=rsqrtf(var+EPSV);
    }
  } else if(b < 1628){
    int i = b-788;
    int d = i>>2, seg = i&3;
    const float4* p = (const float4*)(x2 + d*NHW + seg*36864);
    float s=0.f,q=0.f;
    for(int i2=tid;i2<9216;i2+=256){
      float4 v=p[i2];
      s += v.x+v.y+v.z+v.w;
      q += v.x*v.x+v.y*v.y+v.z*v.z+v.w*v.w;
    }
    __shared__ float ss2[8], sq2[8];
    s=wsum(s); q=wsum(q);
    int w=tid>>5, ln=tid&31;
    if(ln==0){ ss2[w]=s; sq2[w]=q; }
    __syncthreads();
    if(tid==0){
      float S=0.f,Q=0.f;
      #pragma unroll
      for(int i2=0;i2<8;i2++){S+=ss2[i2];Q+=sq2[i2];}
      atomicAdd(&g_accS[d],S); atomicAdd(&g_accQ[d],Q);
    }
  } else {
    int idx = (b-1628)*256 + tid;
    if(idx >= 10*2*9*16*64) return;
    int n   = idx & 63;
    int cp  = (idx>>6) & 15;
    int tap = (idx>>10) % 9;
    int rest= (idx>>10) / 9;
    int half= rest & 1;
    int lk  = rest >> 1;
    int ci0 = half*32 + cp*2;
    float w0 = rw[((lk*CH + n)*CH + ci0  )*9 + tap];
    float w1 = rw[((lk*CH + n)*CH + ci0+1)*9 + tap];
    uint32_t hp, lp;
    bf16split2(w0, w1, hp, lp);
    int o = ((rest*9 + tap)*16 + cp)*72 + n;
    g_wBh[o] = hp; g_wBl[o] = lp;
  }
}

__global__ void k_fin_rs2(){
  int t=threadIdx.x;
  if(t<ND2){
    float mu = g_accS[t]/(float)NHW;
    float var = g_accQ[t]/(float)NHW - mu*mu;
    g_rs2[t] = rsqrtf(var+EPSV);
  }
}

// merged weight fold
__global__ void k_fold(const float* __restrict__ W1, const float* __restrict__ W2){
  int idx = blockIdx.x*256+threadIdx.x;
  if(idx < CH*ND1){
    int c = idx/ND1, d = idx%ND1;
    float rs = g_rs1[d];
    g_W1af[idx] = W1[c*2*ND1 + d]*rs;
    g_W1bf[idx] = W1[c*2*ND1 + ND1 + d]*rs;
  } else {
    int i2 = idx - CH*ND1;
    if(i2 < CH*ND2) g_W2f[i2] = W2[i2]*g_rs2[i2%ND2];
  }
}

__global__ void k_rowcol(const float* __restrict__ x1){
  int c = blockIdx.x, i = threadIdx.x;
  const float* wa = g_W1af + c*ND1;
  const float* wb = g_W1bf + c*ND1;
  float r=0.f, cl=0.f;
  for(int d=0; d<ND1; d++){
    float v = x1[d*LDIM + i];
    r  += wa[d]*v;
    cl += wb[d]*v;
  }
  g_row[c*LDIM+i]=r; g_col[c*LDIM+i]=cl;
}

__global__ void k_rcstats(const float* __restrict__ g1, const float* __restrict__ b1){
  int c = blockIdx.x;
  float sr=0.f,qr=0.f,sc=0.f,qc=0.f;
  for(int i=threadIdx.x;i<LDIM;i+=128){
    float r=g_row[c*LDIM+i], cl=g_col[c*LDIM+i];
    sr+=r; qr+=r*r; sc+=cl; qc+=cl*cl;
  }
  __shared__ float sm4[4][4];
  sr=wsum(sr); qr=wsum(qr); sc=wsum(sc); qc=wsum(qc);
  int w=threadIdx.x>>5, ln=threadIdx.x&31;
  if(ln==0){ sm4[w][0]=sr; sm4[w][1]=qr; sm4[w][2]=sc; sm4[w][3]=qc; }
  __syncthreads();
  if(threadIdx.x==0){
    float Sr=0.f,Qr=0.f,Sc=0.f,Qc=0.f;
    #pragma unroll
    for(int i=0;i<4;i++){Sr+=sm4[i][0];Qr+=sm4[i][1];Sc+=sm4[i][2];Qc+=sm4[i][3];}
    float mr=Sr/(float)LDIM, mc=Sc/(float)LDIM;
    float vr=Qr/(float)LDIM-mr*mr, vc=Qc/(float)LDIM-mc*mc;
    float rs=rsqrtf(vr+vc+EPSV);
    float a=g1[c]*rs;
    g_a1[c]=a; g_c1[c]=b1[c]-(mr+mc)*a;
  }
}

// pair2 GEMM with packed f32x2 + fused stats (set 0)
__global__ void k_pair2(const float* __restrict__ x2){
  extern __shared__ float sm[];
  float* W2T = sm;            // [d][c] 210*64
  float* xs  = sm + 13440;    // 6*256
  int tid=threadIdx.x;
  for(int i=tid;i<13440;i+=256){ int d=i>>6, c=i&63; W2T[i]=g_W2f[c*ND2+d]; }
  int cg = tid>>7, pxl = tid&127;
  int lane = tid&31;
  int pix0 = blockIdx.x*256;
  unsigned long long a0[16], a1[16];
  #pragma unroll
  for(int p=0;p<16;p++){ a0[p]=0ULL; a1[p]=0ULL; }
  __syncthreads();
  for(int d0=0; d0<ND2; d0+=6){
    for(int i=tid;i<384;i+=256)
      ((float4*)xs)[i] = ((const float4*)(x2 + (d0 + (i>>6))*NHW + pix0))[i&63];
    __syncthreads();
    #pragma unroll
    for(int dd=0;dd<6;dd++){
      float2 v = *(const float2*)(xs + dd*256 + pxl*2);
      unsigned long long dv0, dv1;
      asm("mov.b64 %0, {%1,%1};" : "=l"(dv0) : "f"(v.x));
      asm("mov.b64 %0, {%1,%1};" : "=l"(dv1) : "f"(v.y));
      const unsigned long long* wp = (const unsigned long long*)(W2T + (d0+dd)*64 + cg*32);
      #pragma unroll
      for(int p=0;p<16;p++){
        unsigned long long w2 = wp[p];
        asm("fma.rn.f32x2 %0, %1, %2, %0;" : "+l"(a0[p]) : "l"(w2), "l"(dv0));
        asm("fma.rn.f32x2 %0, %1, %2, %0;" : "+l"(a1[p]) : "l"(w2), "l"(dv1));
      }
    }
    __syncthreads();
  }
  int P = pix0 + pxl*2;
  #pragma unroll
  for(int p=0;p<16;p++){
    float l0,h0,l1,h1;
    asm("mov.b64 {%0,%1}, %2;" : "=f"(l0), "=f"(h0) : "l"(a0[p]));
    asm("mov.b64 {%0,%1}, %2;" : "=f"(l1), "=f"(h1) : "l"(a1[p]));
    int c = cg*32 + 2*p;
    g_bufU[c*NHW + P]       = l0;
    g_bufU[c*NHW + P + 1]   = l1;
    g_bufU[(c+1)*NHW + P]   = h0;
    g_bufU[(c+1)*NHW + P+1] = h1;
    // fused stats: warp covers 64 px (lanes x 2) for channels c, c+1
    float s0 = l0+l1, q0 = l0*l0+l1*l1;
    float s1 = h0+h1, q1 = h0*h0+h1*h1;
    #pragma unroll
    for(int off=16; off>0; off>>=1){
      s0 += __shfl_xor_sync(0xffffffffu, s0, off);
      q0 += __shfl_xor_sync(0xffffffffu, q0, off);
      s1 += __shfl_xor_sync(0xffffffffu, s1, off);
      q1 += __shfl_xor_sync(0xffffffffu, q1, off);
    }
    if(lane==0){ REDADD(g_sS+c, s0); REDADD(g_sQ+c, q0); }
    if(lane==1){ REDADD(g_sS+c+1, s1); REDADD(g_sQ+c+1, q1); }
  }
}

// pair stage, f32x2 (a2/c2 from stat set 0) + fused stats (set 1)
__global__ void k_pair(const float* __restrict__ W3,
                       const float* __restrict__ g2, const float* __restrict__ b2){
  extern __shared__ float sm[];
  float* WaT = sm;             // [d][c] stride 66
  float* WbT = sm + 64*66;
  float* p1s = sm + 2*64*66;
  float* p2s = p1s + 4096;
  float* aS2 = p2s + 4096;     // 64
  float* cS2 = aS2 + 64;       // 64
  int tid=threadIdx.x;
  for(int i=tid;i<4096;i+=256){
    int d=i&63, c=i>>6;
    WaT[d*66+c]=W3[c*128+d];
    WbT[d*66+c]=W3[c*128+64+d];
  }
  if(tid<64){ float a,cc; aff_from_stats(g_sS, g_sQ, g2, b2, tid, a, cc); aS2[tid]=a; cS2[tid]=cc; }
  __syncthreads();
  int P0 = blockIdx.x*64;
  int i0 = P0/LDIM, j0 = P0 - i0*LDIM;
  for(int idx=tid;idx<4096;idx+=256){
    int c=idx>>6, px=idx&63;
    float v1 = g_row[c*LDIM+i0] + g_col[c*LDIM+j0+px];
    p1s[idx] = lrelu(g_a1[c]*v1 + g_c1[c]);
    float u = g_bufU[c*NHW + P0 + px];
    p2s[idx] = lrelu(aS2[c]*u + cS2[c]);
  }
  __syncthreads();
  int pi=tid&31, cg=tid>>5;
  unsigned long long acc[8];
  #pragma unroll
  for(int p=0;p<8;p++) acc[p]=0ULL;
  for(int dd=0;dd<64;dd++){
    float2 v1 = *(const float2*)(p1s + dd*64 + pi*2);
    float2 v2 = *(const float2*)(p2s + dd*64 + pi*2);
    unsigned long long s10,s11,s20,s21;
    asm("mov.b64 %0, {%1,%1};" : "=l"(s10) : "f"(v1.x));
    asm("mov.b64 %0, {%1,%1};" : "=l"(s11) : "f"(v1.y));
    asm("mov.b64 %0, {%1,%1};" : "=l"(s20) : "f"(v2.x));
    asm("mov.b64 %0, {%1,%1};" : "=l"(s21) : "f"(v2.y));
    const unsigned long long* wa = (const unsigned long long*)(WaT + dd*66 + cg*8);
    const unsigned long long* wb = (const unsigned long long*)(WbT + dd*66 + cg*8);
    #pragma unroll
    for(int p=0;p<4;p++){
      unsigned long long wA=wa[p], wB=wb[p];
      asm("fma.rn.f32x2 %0, %1, %2, %0;" : "+l"(acc[p*2  ]) : "l"(wA), "l"(s10));
      asm("fma.rn.f32x2 %0, %1, %2, %0;" : "+l"(acc[p*2  ]) : "l"(wB), "l"(s20));
      asm("fma.rn.f32x2 %0, %1, %2, %0;" : "+l"(acc[p*2+1]) : "l"(wA), "l"(s11));
      asm("fma.rn.f32x2 %0, %1, %2, %0;" : "+l"(acc[p*2+1]) : "l"(wB), "l"(s21));
    }
  }
  float sv[16];
  #pragma unroll
  for(int p=0;p<4;p++){
    float l0,h0,l1,h1;
    asm("mov.b64 {%0,%1}, %2;" : "=f"(l0), "=f"(h0) : "l"(acc[p*2]));
    asm("mov.b64 {%0,%1}, %2;" : "=f"(l1), "=f"(h1) : "l"(acc[p*2+1]));
    int c = cg*8 + 2*p;
    int P = P0 + pi*2;
    g_bufX[c*NHW + P]       = l0;
    g_bufX[c*NHW + P+1]     = l1;
    g_bufX[(c+1)*NHW + P]   = h0;
    g_bufX[(c+1)*NHW + P+1] = h1;
    sv[p*4+0] = l0+l1;       sv[p*4+1] = l0*l0+l1*l1;
    sv[p*4+2] = h0+h1;       sv[p*4+3] = h0*h0+h1*h1;
  }
  #pragma unroll
  for(int off=16; off>0; off>>=1){
    #pragma unroll
    for(int i=0;i<16;i++) sv[i] += __shfl_xor_sync(0xffffffffu, sv[i], off);
  }
  if(pi<16){
    int p = pi>>2, h = (pi>>1)&1, sq = pi&1;
    int c = cg*8 + 2*p + h;
    REDADD((sq? g_sQ : g_sS) + 64 + c, sv[pi]);
  }
}

__global__ void k_apply_res(const float* __restrict__ u, const float* __restrict__ res,
                            float* __restrict__ o,
                            const float* __restrict__ sS, const float* __restrict__ sQ,
                            const float* __restrict__ gm, const float* __restrict__ bt){
  int c=blockIdx.y;
  float a,cc; aff_from_stats(sS,sQ,gm,bt,c,a,cc);
  int idx = blockIdx.x*256 + threadIdx.x;
  float4 uv = ((const float4*)(u + c*NHW))[idx];
  float4 rv = ((const float4*)(res + c*NHW))[idx];
  float4 ov;
  ov.x = lrelu(a*uv.x+cc)+rv.x; ov.y = lrelu(a*uv.y+cc)+rv.y;
  ov.z = lrelu(a*uv.z+cc)+rv.z; ov.w = lrelu(a*uv.w+cc)+rv.w;
  ((float4*)(o + c*NHW))[idx] = ov;
}

// ---------------- conv 3x3 dilated 64->64 via mma.sync bf16 hi/lo split ----------------
// 256 threads, 8 warps, occ 2. Fused per-channel stat accumulation in epilogue.
template<int D>
__global__ void __launch_bounds__(256,2)
k_convM(const float* __restrict__ in, float* __restrict__ out,
        const uint32_t* __restrict__ wBh, const uint32_t* __restrict__ wBl,
        const float* __restrict__ sSi, const float* __restrict__ sQi,
        const float* __restrict__ gm,  const float* __restrict__ bt,
        float* __restrict__ sSo, float* __restrict__ sQo,
        const float* __restrict__ resIn, float* __restrict__ resOut){
  constexpr int TW2  = 16+2*D;
  constexpr int PLHW = (D==1)?328:((D==2)?424:584);
  constexpr int TILE_W = 16*PLHW;
  extern __shared__ uint32_t smu[];
  uint32_t* tileH = smu;
  uint32_t* tileL = smu + TILE_W;
  uint32_t* Bh    = smu + 2*TILE_W;     // 2 x 1152
  uint32_t* Bl    = Bh + 2*1152;        // 2 x 1152
  float* aS = (float*)(Bl + 2*1152);    // 64
  float* cS = aS + 64;                  // 64
  float* red = cS + 64;                 // 512

  int tid = threadIdx.x;
  int lane = tid & 31, wid = tid >> 5;
  int wm = wid >> 1, wn = wid & 1;
  int g = lane >> 2, tig = lane & 3;
  int x0 = blockIdx.x*16, y0 = blockIdx.y*16;

  bool doAct = (gm != nullptr);
  bool hasRes = (resIn != nullptr);
  bool wAct = (resOut != nullptr);
  if(tid < 64){
    if(doAct){ float a,cc; aff_from_stats(sSi,sQi,gm,bt,tid,a,cc); aS[tid]=a; cS[tid]=cc; }
    else { aS[tid]=1.f; cS[tid]=0.f; }
  }

  float acc[4][4][4];
  #pragma unroll
  for(int j=0;j<4;j++)
    #pragma unroll
    for(int na=0;na<4;na++)
      #pragma unroll
      for(int q=0;q<4;q++) acc[j][na][q]=0.f;

  for(int half=0; half<2; half++){
    __syncthreads();
    for(int idx=tid; idx<16*TW2*TW2; idx+=256){
      int cp = idx/(TW2*TW2); int rr = idx - cp*(TW2*TW2);
      int r = rr/TW2, c2 = rr - r*TW2;
      int gy = y0 - D + r, gx = x0 - D + c2;
      float v0=0.f, v1=0.f;
      if(((unsigned)gy<384u) && ((unsigned)gx<384u)){
        int ci0 = half*32 + cp*2;
        int off0 = ci0*NHW + gy*LDIM + gx;
        float u0 = in[off0], u1 = in[off0+NHW];
        if(hasRes){
          float t0 = aS[ci0]*u0 + cS[ci0];
          float t1 = aS[ci0+1]*u1 + cS[ci0+1];
          v0 = fmaxf(t0, 0.01f*t0) + resIn[off0];
          v1 = fmaxf(t1, 0.01f*t1) + resIn[off0+NHW];
          if((unsigned)(gy-y0)<16u && (unsigned)(gx-x0)<16u){
            resOut[off0] = v0; resOut[off0+NHW] = v1;
          }
        } else if(doAct){
          float t0 = aS[ci0]*u0 + cS[ci0];     v0 = fmaxf(t0, 0.01f*t0);
          float t1 = aS[ci0+1]*u1 + cS[ci0+1]; v1 = fmaxf(t1, 0.01f*t1);
          if(wAct && (unsigned)(gy-y0)<16u && (unsigned)(gx-x0)<16u){
            resOut[off0] = v0; resOut[off0+NHW] = v1;
          }
        } else { v0=u0; v1=u1; }
      }
      uint32_t hp, lp;
      bf16split2(v0, v1, hp, lp);
      int off = cp*PLHW + r*TW2 + c2;
      tileH[off] = hp; tileL[off] = lp;
    }
    const uint4* bsrcH = (const uint4*)(wBh + (half*9)*1152);
    const uint4* bsrcL = (const uint4*)(wBl + (half*9)*1152);
    for(int i=tid;i<288;i+=256){ ((uint4*)Bh)[i]=bsrcH[i]; ((uint4*)Bl)[i]=bsrcL[i]; }
    __syncthreads();

    for(int tap=0; tap<9; tap++){
      int buf = tap & 1;
      if(tap < 8){
        const uint4* nh = bsrcH + (tap+1)*288;
        const uint4* nl = bsrcL + (tap+1)*288;
        uint4* dh = (uint4*)(Bh + (buf^1)*1152);
        uint4* dl = (uint4*)(Bl + (buf^1)*1152);
        for(int i=tid;i<288;i+=256){ dh[i]=nh[i]; dl[i]=nl[i]; }
      }
      int ky = tap/3, kx = tap - ky*3;
      #pragma unroll
      for(int kc=0;kc<2;kc++){
        uint32_t AH[4][4], AL[4][4];
        const uint32_t* tb = tileH + (kc*8+tig)*PLHW + (ky*D)*TW2 + kx*D + g;
        #pragma unroll
        for(int j=0;j<4;j++){
          const uint32_t* th = tb + (wm*4+j)*TW2;
          AH[j][0]=th[0]; AH[j][1]=th[8]; AH[j][2]=th[4*PLHW]; AH[j][3]=th[4*PLHW+8];
          const uint32_t* tl = th + TILE_W;
          AL[j][0]=tl[0]; AL[j][1]=tl[8]; AL[j][2]=tl[4*PLHW]; AL[j][3]=tl[4*PLHW+8];
        }
        const uint32_t* bbh = Bh + buf*1152 + (kc*8+tig)*72 + wn*32 + g;
        const uint32_t* bbl = Bl + buf*1152 + (kc*8+tig)*72 + wn*32 + g;
        #pragma unroll
        for(int na=0;na<4;na++){
          uint32_t bh0 = bbh[na*8], bh1 = bbh[na*8 + 4*72];
          uint32_t bl0 = bbl[na*8], bl1 = bbl[na*8 + 4*72];
          #pragma unroll
          for(int j=0;j<4;j++) MMA16816(acc[j][na], AH[j], bh0, bh1);
          #pragma unroll
          for(int j=0;j<4;j++) MMA16816(acc[j][na], AH[j], bl0, bl1);
          #pragma unroll
          for(int j=0;j<4;j++) MMA16816(acc[j][na], AL[j], bh0, bh1);
        }
      }
      __syncthreads();
    }
  }
  // epilogue: write output
  #pragma unroll
  for(int j=0;j<4;j++){
    int gy = y0 + wm*4 + j;
    #pragma unroll
    for(int na=0;na<4;na++){
      int co = wn*32 + na*8 + tig*2;
      float* op = out + co*NHW + gy*LDIM + x0;
      op[g]         = acc[j][na][0];
      op[NHW + g]   = acc[j][na][1];
      op[g+8]       = acc[j][na][2];
      op[NHW + g+8] = acc[j][na][3];
    }
  }
  // fused per-channel stats
  float sv[16];
  #pragma unroll
  for(int na=0;na<4;na++){
    #pragma unroll
    for(int par=0;par<2;par++){
      float s=0.f, q=0.f;
      #pragma unroll
      for(int j=0;j<4;j++){
        float v0=acc[j][na][par], v1=acc[j][na][par+2];
        s += v0+v1; q += v0*v0+v1*v1;
      }
      sv[(na*2+par)*2]   = s;
      sv[(na*2+par)*2+1] = q;
    }
  }
  #pragma unroll
  for(int off=4; off<32; off<<=1){
    #pragma unroll
    for(int i=0;i<16;i++) sv[i] += __shfl_xor_sync(0xffffffffu, sv[i], off);
  }
  if(lane<4){
    #pragma unroll
    for(int i=0;i<16;i++) red[wid*64 + lane*16 + i] = sv[i];
  }
  __syncthreads();
  if(tid<128){
    int sq = tid>>6, ch = tid&63;
    int wn_=ch>>5, na_=(ch>>3)&3, tg=(ch>>1)&3, par=ch&1;
    float tot=0.f;
    #pragma unroll
    for(int k=0;k<4;k++) tot += red[(2*k+wn_)*64 + tg*16 + (na_*2+par)*2 + sq];
    REDADD((sq? sQo : sSo)+ch, tot);
  }
}

// ---------------- host ----------------
static void launch_conv(int d, const float* in, float* out,
                        const uint32_t* wh, const uint32_t* wl,
                        const float* sSi, const float* sQi,
                        const float* gm, const float* bt,
                        float* sSo, float* sQo,
                        const float* resIn, float* resOut){
  dim3 g(24,24);
  if(d==1)      k_convM<1><<<g,256,62976>>>(in,out,wh,wl,sSi,sQi,gm,bt,sSo,sQo,resIn,resOut);
  else if(d==2) k_convM<2><<<g,256,75264>>>(in,out,wh,wl,sSi,sQi,gm,bt,sSo,sQo,resIn,resOut);
  else          k_convM<4><<<g,256,95744>>>(in,out,wh,wl,sSi,sQi,gm,bt,sSo,sQo,resIn,resOut);
}

extern "C" void kernel_launch(void* const* d_in, const int* in_sizes, int n_in,
                              void* d_out, int out_size){
  const float* x1 =(const float*)d_in[0];
  const float* x2 =(const float*)d_in[1];
  const float* W1 =(const float*)d_in[2];
  const float* g1 =(const float*)d_in[3];
  const float* b1 =(const float*)d_in[4];
  const float* W2 =(const float*)d_in[5];
  const float* g2 =(const float*)d_in[6];
  const float* b2 =(const float*)d_in[7];
  const float* W3 =(const float*)d_in[8];
  const float* g3 =(const float*)d_in[9];
  const float* b3 =(const float*)d_in[10];
  const float* rw =(const float*)d_in[11];
  const float* rg =(const float*)d_in[13];
  const float* rbe=(const float*)d_in[14];
  float* outp=(float*)d_out;

  float *bufT,*bufU,*bufX,*bufV,*sS,*sQ;
  uint32_t *wBh,*wBl;
  cudaGetSymbolAddress((void**)&bufT, g_bufT);
  cudaGetSymbolAddress((void**)&bufU, g_bufU);
  cudaGetSymbolAddress((void**)&bufX, g_bufX);
  cudaGetSymbolAddress((void**)&bufV, g_bufV);
  cudaGetSymbolAddress((void**)&wBh,  g_wBh);
  cudaGetSymbolAddress((void**)&wBl,  g_wBl);
  cudaGetSymbolAddress((void**)&sS,   g_sS);
  cudaGetSymbolAddress((void**)&sQ,   g_sQ);

  cudaFuncSetAttribute(k_convM<1>, cudaFuncAttributeMaxDynamicSharedMemorySize, 62976);
  cudaFuncSetAttribute(k_convM<2>, cudaFuncAttributeMaxDynamicSharedMemorySize, 75264);
  cudaFuncSetAttribute(k_convM<4>, cudaFuncAttributeMaxDynamicSharedMemorySize, 95744);
  cudaFuncSetAttribute(k_pair2,    cudaFuncAttributeMaxDynamicSharedMemorySize, 61440);
  cudaFuncSetAttribute(k_pair,     cudaFuncAttributeMaxDynamicSharedMemorySize, 67584);

  k_zero<<<1,1024>>>();
  k_front<<<2348,256>>>(x1, x2, rw);
  k_fin_rs2<<<1,256>>>();
  k_fold<<<(CH*ND1+CH*ND2+255)/256,256>>>(W1, W2);
  k_rowcol<<<64,384>>>(x1);
  k_rcstats<<<64,128>>>(g1,b1);
  k_pair2<<<576,256,61440>>>(x2);                              // writes set 0 (fused)
  k_pair<<<2304,256,67584>>>(W3, g2, b2);                      // uses set 0, writes set 1 (fused)

  const int dil[5]={1,2,4,2,1};
  float* resBuf[2] = {bufV, bufX};
  int cur = 0;   // bufV will hold the activated pair output (residual) after conv1-l0
  for(int l=0;l<5;l++){
    int d=dil[l];
    const uint32_t* wh0 = wBh + (l*2  )*20736;
    const uint32_t* wl0 = wBl + (l*2  )*20736;
    const uint32_t* wh1 = wBh + (l*2+1)*20736;
    const uint32_t* wl1 = wBl + (l*2+1)*20736;
    float* s0S = sS + (2+2*l)*64;  float* s0Q = sQ + (2+2*l)*64;
    float* s1S = sS + (3+2*l)*64;  float* s1Q = sQ + (3+2*l)*64;
    if(l==0){
      launch_conv(d, bufX, bufT, wh0, wl0,
                  sS+1*64, sQ+1*64, g3, b3, s0S, s0Q, nullptr, bufV);
    } else {
      float* sPS = sS + (1+2*l)*64;  float* sPQ = sQ + (1+2*l)*64;
      launch_conv(d, bufU, bufT, wh0, wl0,
                  sPS, sPQ, rg+(2*l-1)*CH, rbe+(2*l-1)*CH, s0S, s0Q,
                  resBuf[cur], resBuf[cur^1]);
      cur ^= 1;
    }
    launch_conv(d, bufT, bufU, wh1, wl1,
                s0S, s0Q, rg+(2*l)*CH, rbe+(2*l)*CH, s1S, s1Q, nullptr,nullptr);
  }
  k_apply_res<<<dim3(144,64),256>>>(bufU, resBuf[cur], outp,
                                    sS+11*64, sQ+11*64, rg+9*CH, rbe+9*CH);
}

// round 13
// speedup vs baseline: 1.0359x; 1.0359x over previous
#include <cuda_runtime.h>
#include <cstdint>

constexpr int LDIM = 384;
constexpr int NHW  = 147456;   // 384*384
constexpr int CH   = 64;
constexpr int ND1  = 788;
constexpr int ND2  = 210;
#define EPSV 1e-5f

// ---------------- device scratch (static, no allocations) ----------------
__device__ float g_bufT[CH*NHW];
__device__ float g_bufU[CH*NHW];
__device__ float g_bufX[CH*NHW];
__device__ float g_bufV[CH*NHW];   // residual ping-pong partner of bufX
__device__ float g_rs1[ND1];
__device__ float g_W1af[CH*ND1];
__device__ float g_W1bf[CH*ND1];
__device__ float g_W2f[CH*ND2];
__device__ float g_row[CH*LDIM];
__device__ float g_col[CH*LDIM];
__device__ float g_a1[CH], g_c1[CH];
__device__ float g_accS[ND2], g_accQ[ND2];
// 12 per-channel stat sets (sum / sumsq), each written once per run
__device__ float g_sS[12*64];
__device__ float g_sQ[12*64];
// conv weights as B-fragment words: [lk][half][tap][cipair 16][72 (64 used)]
__device__ uint32_t g_wBh[10*2*9*16*72];
__device__ uint32_t g_wBl[10*2*9*16*72];

__device__ __forceinline__ float lrelu(float v){ return fmaxf(v, 0.01f*v); }

__device__ __forceinline__ float wsum(float v){
  #pragma unroll
  for(int o=16;o>0;o>>=1) v += __shfl_down_sync(0xffffffffu, v, o);
  return v;
}

__device__ __forceinline__ void bf16split2(float v0, float v1, uint32_t& hp, uint32_t& lp){
  asm("cvt.rn.bf16x2.f32 %0, %1, %2;" : "=r"(hp) : "f"(v1), "f"(v0));
  float h0 = __uint_as_float(hp<<16);
  float h1 = __uint_as_float(hp & 0xffff0000u);
  float l0 = v0 - h0, l1 = v1 - h1;
  asm("cvt.rn.bf16x2.f32 %0, %1, %2;" : "=r"(lp) : "f"(l1), "f"(l0));
}

#define MMA16816(d, a, b0, b1) \
  asm volatile("mma.sync.aligned.m16n8k16.row.col.f32.bf16.bf16.f32 " \
    "{%0,%1,%2,%3}, {%4,%5,%6,%7}, {%8,%9}, {%0,%1,%2,%3};" \
    : "+f"((d)[0]),"+f"((d)[1]),"+f"((d)[2]),"+f"((d)[3]) \
    : "r"((a)[0]),"r"((a)[1]),"r"((a)[2]),"r"((a)[3]), "r"(b0),"r"(b1))

#define REDADD(p, v) asm volatile("red.global.add.f32 [%0], %1;" :: "l"(p), "f"(v) : "memory")

__device__ __forceinline__ void aff_from_stats(const float* sS, const float* sQ,
                                               const float* gm, const float* bt,
                                               int c, float& a, float& cc){
  float mu = sS[c]*(1.f/(float)NHW);
  float var = sQ[c]*(1.f/(float)NHW) - mu*mu;
  a = gm[c]*rsqrtf(var+EPSV);
  cc = bt[c]-mu*a;
}

// ---------------- small kernels ----------------
__global__ void k_zero(){
  int t = threadIdx.x;
  if(t < 768){ g_sS[t]=0.f; g_sQ[t]=0.f; }
  if(t < ND2){ g_accS[t]=0.f; g_accQ[t]=0.f; }
}

// merged front kernel: blocks [0,788) stats1d, [788,1628) stats2, [1628,2348) prepB
__global__ void k_front(const float* __restrict__ x1, const float* __restrict__ x2,
                        const float* __restrict__ rw){
  int b = blockIdx.x;
  int tid = threadIdx.x;
  if(b < 788){
    const float* p = x1 + b*LDIM;
    float s=0.f,q=0.f;
    for(int i=tid;i<LDIM;i+=256){ float v=p[i]; s+=v; q+=v*v; }
    __shared__ float ss[8], sq[8];
    s = wsum(s); q = wsum(q);
    int w = tid>>5, ln = tid&31;
    if(ln==0){ ss[w]=s; sq[w]=q; }
    __syncthreads();
    if(tid==0){
      float S=0.f,Q=0.f;
      #pragma unroll
      for(int i=0;i<8;i++){S+=ss[i];Q+=sq[i];}
      float mu=S/(float)LDIM; float var=Q/(float)LDIM-mu*mu;
      g_rs1[b]=rsqrtf(var+EPSV);
    }
  } else if(b < 1628){
    int i = b-788;
    int d = i>>2, seg = i&3;
    const float4* p = (const float4*)(x2 + d*NHW + seg*36864);
    float s=0.f,q=0.f;
    for(int i2=tid;i2<9216;i2+=256){
      float4 v=p[i2];
      s += v.x+v.y+v.z+v.w;
      q += v.x*v.x+v.y*v.y+v.z*v.z+v.w*v.w;
    }
    __shared__ float ss2[8], sq2[8];
    s=wsum(s); q=wsum(q);
    int w=tid>>5, ln=tid&31;
    if(ln==0){ ss2[w]=s; sq2[w]=q; }
    __syncthreads();
    if(tid==0){
      float S=0.f,Q=0.f;
      #pragma unroll
      for(int i2=0;i2<8;i2++){S+=ss2[i2];Q+=sq2[i2];}
      atomicAdd(&g_accS[d],S); atomicAdd(&g_accQ[d],Q);
    }
  } else {
    int idx = (b-1628)*256 + tid;
    if(idx >= 10*2*9*16*64) return;
    int n   = idx & 63;
    int cp  = (idx>>6) & 15;
    int tap = (idx>>10) % 9;
    int rest= (idx>>10) / 9;
    int half= rest & 1;
    int lk  = rest >> 1;
    int ci0 = half*32 + cp*2;
    float w0 = rw[((lk*CH + n)*CH + ci0  )*9 + tap];
    float w1 = rw[((lk*CH + n)*CH + ci0+1)*9 + tap];
    uint32_t hp, lp;
    bf16split2(w0, w1, hp, lp);
    int o = ((rest*9 + tap)*16 + cp)*72 + n;
    g_wBh[o] = hp; g_wBl[o] = lp;
  }
}

// merged weight fold (rs2 computed inline from accumulated stats)
__global__ void k_fold(const float* __restrict__ W1, const float* __restrict__ W2){
  int idx = blockIdx.x*256+threadIdx.x;
  if(idx < CH*ND1){
    int c = idx/ND1, d = idx%ND1;
    float rs = g_rs1[d];
    g_W1af[idx] = W1[c*2*ND1 + d]*rs;
    g_W1bf[idx] = W1[c*2*ND1 + ND1 + d]*rs;
  } else {
    int i2 = idx - CH*ND1;
    if(i2 < CH*ND2){
      int d = i2%ND2;
      float mu = g_accS[d]*(1.f/(float)NHW);
      float var = g_accQ[d]*(1.f/(float)NHW) - mu*mu;
      g_W2f[i2] = W2[i2]*rsqrtf(var+EPSV);
    }
  }
}

// rowcol + fused rc-stats (block c holds all 384 positions)
__global__ void k_rowcol(const float* __restrict__ x1,
                         const float* __restrict__ g1, const float* __restrict__ b1){
  int c = blockIdx.x, i = threadIdx.x;   // 384 threads
  const float* wa = g_W1af + c*ND1;
  const float* wb = g_W1bf + c*ND1;
  float r=0.f, cl=0.f;
  for(int d=0; d<ND1; d++){
    float v = x1[d*LDIM + i];
    r  += wa[d]*v;
    cl += wb[d]*v;
  }
  g_row[c*LDIM+i]=r; g_col[c*LDIM+i]=cl;
  // fused stats: mu/var of row and col over i
  float sr=r, qr=r*r, sc=cl, qc=cl*cl;
  sr=wsum(sr); qr=wsum(qr); sc=wsum(sc); qc=wsum(qc);
  __shared__ float sm4[12][4];
  int w=i>>5, ln=i&31;
  if(ln==0){ sm4[w][0]=sr; sm4[w][1]=qr; sm4[w][2]=sc; sm4[w][3]=qc; }
  __syncthreads();
  if(i==0){
    float Sr=0.f,Qr=0.f,Sc=0.f,Qc=0.f;
    #pragma unroll
    for(int k=0;k<12;k++){Sr+=sm4[k][0];Qr+=sm4[k][1];Sc+=sm4[k][2];Qc+=sm4[k][3];}
    float mr=Sr/(float)LDIM, mc=Sc/(float)LDIM;
    float vr=Qr/(float)LDIM-mr*mr, vc=Qc/(float)LDIM-mc*mc;
    float rs=rsqrtf(vr+vc+EPSV);
    float a=g1[c]*rs;
    g_a1[c]=a; g_c1[c]=b1[c]-(mr+mc)*a;
  }
}

// pair2 GEMM with packed f32x2
__global__ void k_pair2(const float* __restrict__ x2){
  extern __shared__ float sm[];
  float* W2T = sm;            // [d][c] 210*64
  float* xs  = sm + 13440;    // 6*256
  int tid=threadIdx.x;
  for(int i=tid;i<13440;i+=256){ int d=i>>6, c=i&63; W2T[i]=g_W2f[c*ND2+d]; }
  int cg = tid>>7, pxl = tid&127;
  int pix0 = blockIdx.x*256;
  unsigned long long a0[16], a1[16];
  #pragma unroll
  for(int p=0;p<16;p++){ a0[p]=0ULL; a1[p]=0ULL; }
  __syncthreads();
  for(int d0=0; d0<ND2; d0+=6){
    for(int i=tid;i<384;i+=256)
      ((float4*)xs)[i] = ((const float4*)(x2 + (d0 + (i>>6))*NHW + pix0))[i&63];
    __syncthreads();
    #pragma unroll
    for(int dd=0;dd<6;dd++){
      float2 v = *(const float2*)(xs + dd*256 + pxl*2);
      unsigned long long dv0, dv1;
      asm("mov.b64 %0, {%1,%1};" : "=l"(dv0) : "f"(v.x));
      asm("mov.b64 %0, {%1,%1};" : "=l"(dv1) : "f"(v.y));
      const unsigned long long* wp = (const unsigned long long*)(W2T + (d0+dd)*64 + cg*32);
      #pragma unroll
      for(int p=0;p<16;p++){
        unsigned long long w2 = wp[p];
        asm("fma.rn.f32x2 %0, %1, %2, %0;" : "+l"(a0[p]) : "l"(w2), "l"(dv0));
        asm("fma.rn.f32x2 %0, %1, %2, %0;" : "+l"(a1[p]) : "l"(w2), "l"(dv1));
      }
    }
    __syncthreads();
  }
  int P = pix0 + pxl*2;
  #pragma unroll
  for(int p=0;p<16;p++){
    float l0,h0,l1,h1;
    asm("mov.b64 {%0,%1}, %2;" : "=f"(l0), "=f"(h0) : "l"(a0[p]));
    asm("mov.b64 {%0,%1}, %2;" : "=f"(l1), "=f"(h1) : "l"(a1[p]));
    int c = cg*32 + 2*p;
    g_bufU[c*NHW + P]       = l0;
    g_bufU[c*NHW + P + 1]   = l1;
    g_bufU[(c+1)*NHW + P]   = h0;
    g_bufU[(c+1)*NHW + P+1] = h1;
  }
}

// per-channel sum/sumsq accumulate into a stat set (float4)
__global__ void k_cstats(const float* __restrict__ buf, float* __restrict__ sS, float* __restrict__ sQ){
  int c=blockIdx.x, seg=blockIdx.y;
  const float4* p = (const float4*)(buf + c*NHW + seg*18432);
  float s=0.f,q=0.f;
  for(int i=threadIdx.x;i<4608;i+=256){
    float4 v=p[i];
    s += v.x+v.y+v.z+v.w;
    q += v.x*v.x+v.y*v.y+v.z*v.z+v.w*v.w;
  }
  __shared__ float ss[8], sq[8];
  s=wsum(s); q=wsum(q);
  int w=threadIdx.x>>5, ln=threadIdx.x&31;
  if(ln==0){ ss[w]=s; sq[w]=q; }
  __syncthreads();
  if(threadIdx.x==0){
    float S=0.f,Q=0.f;
    #pragma unroll
    for(int i=0;i<8;i++){S+=ss[i];Q+=sq[i];}
    atomicAdd(&sS[c],S); atomicAdd(&sQ[c],Q);
  }
}

// pair stage, f32x2 (a2/c2 computed inline from stat set 0)
__global__ void k_pair(const float* __restrict__ W3,
                       const float* __restrict__ g2, const float* __restrict__ b2){
  extern __shared__ float sm[];
  float* WaT = sm;             // [d][c] stride 66
  float* WbT = sm + 64*66;
  float* p1s = sm + 2*64*66;
  float* p2s = p1s + 4096;
  float* aS2 = p2s + 4096;     // 64
  float* cS2 = aS2 + 64;       // 64
  int tid=threadIdx.x;
  for(int i=tid;i<4096;i+=256){
    int d=i&63, c=i>>6;
    WaT[d*66+c]=W3[c*128+d];
    WbT[d*66+c]=W3[c*128+64+d];
  }
  if(tid<64){ float a,cc; aff_from_stats(g_sS, g_sQ, g2, b2, tid, a, cc); aS2[tid]=a; cS2[tid]=cc; }
  __syncthreads();
  int P0 = blockIdx.x*64;
  int i0 = P0/LDIM, j0 = P0 - i0*LDIM;
  for(int idx=tid;idx<4096;idx+=256){
    int c=idx>>6, px=idx&63;
    float v1 = g_row[c*LDIM+i0] + g_col[c*LDIM+j0+px];
    p1s[idx] = lrelu(g_a1[c]*v1 + g_c1[c]);
    float u = g_bufU[c*NHW + P0 + px];
    p2s[idx] = lrelu(aS2[c]*u + cS2[c]);
  }
  __syncthreads();
  int pi=tid&31, cg=tid>>5;
  unsigned long long acc[8];
  #pragma unroll
  for(int p=0;p<8;p++) acc[p]=0ULL;
  for(int dd=0;dd<64;dd++){
    float2 v1 = *(const float2*)(p1s + dd*64 + pi*2);
    float2 v2 = *(const float2*)(p2s + dd*64 + pi*2);
    unsigned long long s10,s11,s20,s21;
    asm("mov.b64 %0, {%1,%1};" : "=l"(s10) : "f"(v1.x));
    asm("mov.b64 %0, {%1,%1};" : "=l"(s11) : "f"(v1.y));
    asm("mov.b64 %0, {%1,%1};" : "=l"(s20) : "f"(v2.x));
    asm("mov.b64 %0, {%1,%1};" : "=l"(s21) : "f"(v2.y));
    const unsigned long long* wa = (const unsigned long long*)(WaT + dd*66 + cg*8);
    const unsigned long long* wb = (const unsigned long long*)(WbT + dd*66 + cg*8);
    #pragma unroll
    for(int p=0;p<4;p++){
      unsigned long long wA=wa[p], wB=wb[p];
      asm("fma.rn.f32x2 %0, %1, %2, %0;" : "+l"(acc[p*2  ]) : "l"(wA), "l"(s10));
      asm("fma.rn.f32x2 %0, %1, %2, %0;" : "+l"(acc[p*2  ]) : "l"(wB), "l"(s20));
      asm("fma.rn.f32x2 %0, %1, %2, %0;" : "+l"(acc[p*2+1]) : "l"(wA), "l"(s11));
      asm("fma.rn.f32x2 %0, %1, %2, %0;" : "+l"(acc[p*2+1]) : "l"(wB), "l"(s21));
    }
  }
  #pragma unroll
  for(int p=0;p<4;p++){
    #pragma unroll
    for(int q=0;q<2;q++){
      float lo,hi;
      asm("mov.b64 {%0,%1}, %2;" : "=f"(lo), "=f"(hi) : "l"(acc[p*2+q]));
      int c = cg*8 + 2*p;
      int P = P0 + pi*2 + q;
      g_bufX[c*NHW + P]     = lo;
      g_bufX[(c+1)*NHW + P] = hi;
    }
  }
}

__global__ void k_apply_res(const float* __restrict__ u, const float* __restrict__ res,
                            float* __restrict__ o,
                            const float* __restrict__ sS, const float* __restrict__ sQ,
                            const float* __restrict__ gm, const float* __restrict__ bt){
  int c=blockIdx.y;
  float a,cc; aff_from_stats(sS,sQ,gm,bt,c,a,cc);
  int idx = blockIdx.x*256 + threadIdx.x;
  float4 uv = ((const float4*)(u + c*NHW))[idx];
  float4 rv = ((const float4*)(res + c*NHW))[idx];
  float4 ov;
  ov.x = lrelu(a*uv.x+cc)+rv.x; ov.y = lrelu(a*uv.y+cc)+rv.y;
  ov.z = lrelu(a*uv.z+cc)+rv.z; ov.w = lrelu(a*uv.w+cc)+rv.w;
  ((float4*)(o + c*NHW))[idx] = ov;
}

// ---------------- conv 3x3 dilated 64->64 via mma.sync bf16 hi/lo split ----------------
// 256 threads, 8 warps, occ 2. Fused per-channel stat accumulation in epilogue.
template<int D>
__global__ void __launch_bounds__(256,2)
k_convM(const float* __restrict__ in, float* __restrict__ out,
        const uint32_t* __restrict__ wBh, const uint32_t* __restrict__ wBl,
        const float* __restrict__ sSi, const float* __restrict__ sQi,
        const float* __restrict__ gm,  const float* __restrict__ bt,
        float* __restrict__ sSo, float* __restrict__ sQo,
        const float* __restrict__ resIn, float* __restrict__ resOut){
  constexpr int TW2  = 16+2*D;
  constexpr int PLHW = (D==1)?328:((D==2)?424:584);
  constexpr int TILE_W = 16*PLHW;
  extern __shared__ uint32_t smu[];
  uint32_t* tileH = smu;
  uint32_t* tileL = smu + TILE_W;
  uint32_t* Bh    = smu + 2*TILE_W;     // 2 x 1152
  uint32_t* Bl    = Bh + 2*1152;        // 2 x 1152
  float* aS = (float*)(Bl + 2*1152);    // 64
  float* cS = aS + 64;                  // 64
  float* red = cS + 64;                 // 512

  int tid = threadIdx.x;
  int lane = tid & 31, wid = tid >> 5;
  int wm = wid >> 1, wn = wid & 1;
  int g = lane >> 2, tig = lane & 3;
  int x0 = blockIdx.x*16, y0 = blockIdx.y*16;

  bool doAct = (gm != nullptr);
  bool hasRes = (resIn != nullptr);
  bool wAct = (resOut != nullptr);
  if(tid < 64){
    if(doAct){ float a,cc; aff_from_stats(sSi,sQi,gm,bt,tid,a,cc); aS[tid]=a; cS[tid]=cc; }
    else { aS[tid]=1.f; cS[tid]=0.f; }
  }

  float acc[4][4][4];
  #pragma unroll
  for(int j=0;j<4;j++)
    #pragma unroll
    for(int na=0;na<4;na++)
      #pragma unroll
      for(int q=0;q<4;q++) acc[j][na][q]=0.f;

  for(int half=0; half<2; half++){
    __syncthreads();
    for(int idx=tid; idx<16*TW2*TW2; idx+=256){
      int cp = idx/(TW2*TW2); int rr = idx - cp*(TW2*TW2);
      int r = rr/TW2, c2 = rr - r*TW2;
      int gy = y0 - D + r, gx = x0 - D + c2;
      float v0=0.f, v1=0.f;
      if(((unsigned)gy<384u) && ((unsigned)gx<384u)){
        int ci0 = half*32 + cp*2;
        int off0 = ci0*NHW + gy*LDIM + gx;
        float u0 = in[off0], u1 = in[off0+NHW];
        if(hasRes){
          float t0 = aS[ci0]*u0 + cS[ci0];
          float t1 = aS[ci0+1]*u1 + cS[ci0+1];
          v0 = fmaxf(t0, 0.01f*t0) + resIn[off0];
          v1 = fmaxf(t1, 0.01f*t1) + resIn[off0+NHW];
          if((unsigned)(gy-y0)<16u && (unsigned)(gx-x0)<16u){
            resOut[off0] = v0; resOut[off0+NHW] = v1;
          }
        } else if(doAct){
          float t0 = aS[ci0]*u0 + cS[ci0];     v0 = fmaxf(t0, 0.01f*t0);
          float t1 = aS[ci0+1]*u1 + cS[ci0+1]; v1 = fmaxf(t1, 0.01f*t1);
          if(wAct && (unsigned)(gy-y0)<16u && (unsigned)(gx-x0)<16u){
            resOut[off0] = v0; resOut[off0+NHW] = v1;
          }
        } else { v0=u0; v1=u1; }
      }
      uint32_t hp, lp;
      bf16split2(v0, v1, hp, lp);
      int off = cp*PLHW + r*TW2 + c2;
      tileH[off] = hp; tileL[off] = lp;
    }
    const uint4* bsrcH = (const uint4*)(wBh + (half*9)*1152);
    const uint4* bsrcL = (const uint4*)(wBl + (half*9)*1152);
    for(int i=tid;i<288;i+=256){ ((uint4*)Bh)[i]=bsrcH[i]; ((uint4*)Bl)[i]=bsrcL[i]; }
    __syncthreads();

    for(int tap=0; tap<9; tap++){
      int buf = tap & 1;
      if(tap < 8){
        const uint4* nh = bsrcH + (tap+1)*288;
        const uint4* nl = bsrcL + (tap+1)*288;
        uint4* dh = (uint4*)(Bh + (buf^1)*1152);
        uint4* dl = (uint4*)(Bl + (buf^1)*1152);
        for(int i=tid;i<288;i+=256){ dh[i]=nh[i]; dl[i]=nl[i]; }
      }
      int ky = tap/3, kx = tap - ky*3;
      #pragma unroll
      for(int kc=0;kc<2;kc++){
        uint32_t AH[4][4], AL[4][4];
        const uint32_t* tb = tileH + (kc*8+tig)*PLHW + (ky*D)*TW2 + kx*D + g;
        #pragma unroll
        for(int j=0;j<4;j++){
          const uint32_t* th = tb + (wm*4+j)*TW2;
          AH[j][0]=th[0]; AH[j][1]=th[8]; AH[j][2]=th[4*PLHW]; AH[j][3]=th[4*PLHW+8];
          const uint32_t* tl = th + TILE_W;
          AL[j][0]=tl[0]; AL[j][1]=tl[8]; AL[j][2]=tl[4*PLHW]; AL[j][3]=tl[4*PLHW+8];
        }
        const uint32_t* bbh = Bh + buf*1152 + (kc*8+tig)*72 + wn*32 + g;
        const uint32_t* bbl = Bl + buf*1152 + (kc*8+tig)*72 + wn*32 + g;
        #pragma unroll
        for(int na=0;na<4;na++){
          uint32_t bh0 = bbh[na*8], bh1 = bbh[na*8 + 4*72];
          uint32_t bl0 = bbl[na*8], bl1 = bbl[na*8 + 4*72];
          #pragma unroll
          for(int j=0;j<4;j++) MMA16816(acc[j][na], AH[j], bh0, bh1);
          #pragma unroll
          for(int j=0;j<4;j++) MMA16816(acc[j][na], AH[j], bl0, bl1);
          #pragma unroll
          for(int j=0;j<4;j++) MMA16816(acc[j][na], AL[j], bh0, bh1);
        }
      }
      __syncthreads();
    }
  }
  // epilogue: write output
  #pragma unroll
  for(int j=0;j<4;j++){
    int gy = y0 + wm*4 + j;
    #pragma unroll
    for(int na=0;na<4;na++){
      int co = wn*32 + na*8 + tig*2;
      float* op = out + co*NHW + gy*LDIM + x0;
      op[g]         = acc[j][na][0];
      op[NHW + g]   = acc[j][na][1];
      op[g+8]       = acc[j][na][2];
      op[NHW + g+8] = acc[j][na][3];
    }
  }
  // fused per-channel stats
  float sv[16];
  #pragma unroll
  for(int na=0;na<4;na++){
    #pragma unroll
    for(int par=0;par<2;par++){
      float s=0.f, q=0.f;
      #pragma unroll
      for(int j=0;j<4;j++){
        float v0=acc[j][na][par], v1=acc[j][na][par+2];
        s += v0+v1; q += v0*v0+v1*v1;
      }
      sv[(na*2+par)*2]   = s;
      sv[(na*2+par)*2+1] = q;
    }
  }
  #pragma unroll
  for(int off=4; off<32; off<<=1){
    #pragma unroll
    for(int i=0;i<16;i++) sv[i] += __shfl_xor_sync(0xffffffffu, sv[i], off);
  }
  if(lane<4){
    #pragma unroll
    for(int i=0;i<16;i++) red[wid*64 + lane*16 + i] = sv[i];
  }
  __syncthreads();
  if(tid<128){
    int sq = tid>>6, ch = tid&63;
    int wn_=ch>>5, na_=(ch>>3)&3, tg=(ch>>1)&3, par=ch&1;
    float tot=0.f;
    #pragma unroll
    for(int k=0;k<4;k++) tot += red[(2*k+wn_)*64 + tg*16 + (na_*2+par)*2 + sq];
    REDADD((sq? sQo : sSo)+ch, tot);
  }
}

// ---------------- host ----------------
static void launch_conv(int d, const float* in, float* out,
                        const uint32_t* wh, const uint32_t* wl,
                        const float* sSi, const float* sQi,
                        const float* gm, const float* bt,
                        float* sSo, float* sQo,
                        const float* resIn, float* resOut){
  dim3 g(24,24);
  if(d==1)      k_convM<1><<<g,256,62976>>>(in,out,wh,wl,sSi,sQi,gm,bt,sSo,sQo,resIn,resOut);
  else if(d==2) k_convM<2><<<g,256,75264>>>(in,out,wh,wl,sSi,sQi,gm,bt,sSo,sQo,resIn,resOut);
  else          k_convM<4><<<g,256,95744>>>(in,out,wh,wl,sSi,sQi,gm,bt,sSo,sQo,resIn,resOut);
}

extern "C" void kernel_launch(void* const* d_in, const int* in_sizes, int n_in,
                              void* d_out, int out_size){
  const float* x1 =(const float*)d_in[0];
  const float* x2 =(const float*)d_in[1];
  const float* W1 =(const float*)d_in[2];
  const float* g1 =(const float*)d_in[3];
  const float* b1 =(const float*)d_in[4];
  const float* W2 =(const float*)d_in[5];
  const float* g2 =(const float*)d_in[6];
  const float* b2 =(const float*)d_in[7];
  const float* W3 =(const float*)d_in[8];
  const float* g3 =(const float*)d_in[9];
  const float* b3 =(const float*)d_in[10];
  const float* rw =(const float*)d_in[11];
  const float* rg =(const float*)d_in[13];
  const float* rbe=(const float*)d_in[14];
  float* outp=(float*)d_out;

  float *bufT,*bufU,*bufX,*bufV,*sS,*sQ;
  uint32_t *wBh,*wBl;
  cudaGetSymbolAddress((void**)&bufT, g_bufT);
  cudaGetSymbolAddress((void**)&bufU, g_bufU);
  cudaGetSymbolAddress((void**)&bufX, g_bufX);
  cudaGetSymbolAddress((void**)&bufV, g_bufV);
  cudaGetSymbolAddress((void**)&wBh,  g_wBh);
  cudaGetSymbolAddress((void**)&wBl,  g_wBl);
  cudaGetSymbolAddress((void**)&sS,   g_sS);
  cudaGetSymbolAddress((void**)&sQ,   g_sQ);

  cudaFuncSetAttribute(k_convM<1>, cudaFuncAttributeMaxDynamicSharedMemorySize, 62976);
  cudaFuncSetAttribute(k_convM<2>, cudaFuncAttributeMaxDynamicSharedMemorySize, 75264);
  cudaFuncSetAttribute(k_convM<4>, cudaFuncAttributeMaxDynamicSharedMemorySize, 95744);
  cudaFuncSetAttribute(k_pair2,    cudaFuncAttributeMaxDynamicSharedMemorySize, 61440);
  cudaFuncSetAttribute(k_pair,     cudaFuncAttributeMaxDynamicSharedMemorySize, 67584);

  k_zero<<<1,1024>>>();
  k_front<<<2348,256>>>(x1, x2, rw);
  k_fold<<<(CH*ND1+CH*ND2+255)/256,256>>>(W1, W2);
  k_rowcol<<<64,384>>>(x1, g1, b1);
  k_pair2<<<576,256,61440>>>(x2);
  k_cstats<<<dim3(64,8),256>>>(bufU, sS+0*64, sQ+0*64);       // set 0: pair2 out
  k_pair<<<2304,256,67584>>>(W3, g2, b2);                      // uses set 0
  k_cstats<<<dim3(64,8),256>>>(bufX, sS+1*64, sQ+1*64);       // set 1: pair out (raw)

  const int dil[5]={1,2,4,2,1};
  float* resBuf[2] = {bufV, bufX};
  int cur = 0;   // bufV will hold the activated pair output (residual) after conv1-l0
  for(int l=0;l<5;l++){
    int d=dil[l];
    const uint32_t* wh0 = wBh + (l*2  )*20736;
    const uint32_t* wl0 = wBl + (l*2  )*20736;
    const uint32_t* wh1 = wBh + (l*2+1)*20736;
    const uint32_t* wl1 = wBl + (l*2+1)*20736;
    float* s0S = sS + (2+2*l)*64;  float* s0Q = sQ + (2+2*l)*64;
    float* s1S = sS + (3+2*l)*64;  float* s1Q = sQ + (3+2*l)*64;
    if(l==0){
      launch_conv(d, bufX, bufT, wh0, wl0,
                  sS+1*64, sQ+1*64, g3, b3, s0S, s0Q, nullptr, bufV);
    } else {
      float* sPS = sS + (1+2*l)*64;  float* sPQ = sQ + (1+2*l)*64;
      launch_conv(d, bufU, bufT, wh0, wl0,
                  sPS, sPQ, rg+(2*l-1)*CH, rbe+(2*l-1)*CH, s0S, s0Q,
                  resBuf[cur], resBuf[cur^1]);
      cur ^= 1;
    }
    launch_conv(d, bufT, bufU, wh1, wl1,
                s0S, s0Q, rg+(2*l)*CH, rbe+(2*l)*CH, s1S, s1Q, nullptr,nullptr);
  }
  k_apply_res<<<dim3(144,64),256>>>(bufU, resBuf[cur], outp,
                                    sS+11*64, sQ+11*64, rg+9*CH, rbe+9*CH);
}

// round 14
// speedup vs baseline: 1.0386x; 1.0026x over previous
#include <cuda_runtime.h>
#include <cstdint>

constexpr int LDIM = 384;
constexpr int NHW  = 147456;   // 384*384
constexpr int CH   = 64;
constexpr int ND1  = 788;
constexpr int ND2  = 210;
#define EPSV 1e-5f

// ---------------- device scratch (static, no allocations) ----------------
__device__ float g_bufT[CH*NHW];
__device__ float g_bufU[CH*NHW];
__device__ float g_bufX[CH*NHW];
__device__ float g_bufV[CH*NHW];   // residual ping-pong partner of bufX
__device__ float g_rs1[ND1];
__device__ float g_W1af[CH*ND1];
__device__ float g_W1bf[CH*ND1];
__device__ float g_W2f[CH*ND2];
__device__ float g_row[CH*LDIM];
__device__ float g_col[CH*LDIM];
__device__ float g_a1[CH], g_c1[CH];
__device__ float g_accS[ND2], g_accQ[ND2];
// 12 per-channel stat sets (sum / sumsq), each written once per run
__device__ float g_sS[12*64];
__device__ float g_sQ[12*64];
// conv weights as B-fragment words: [lk][half][tap][cipair 16][72 (64 used)]
__device__ uint32_t g_wBh[10*2*9*16*72];
__device__ uint32_t g_wBl[10*2*9*16*72];

__device__ __forceinline__ float lrelu(float v){ return fmaxf(v, 0.01f*v); }

__device__ __forceinline__ float wsum(float v){
  #pragma unroll
  for(int o=16;o>0;o>>=1) v += __shfl_down_sync(0xffffffffu, v, o);
  return v;
}

__device__ __forceinline__ void bf16split2(float v0, float v1, uint32_t& hp, uint32_t& lp){
  asm("cvt.rn.bf16x2.f32 %0, %1, %2;" : "=r"(hp) : "f"(v1), "f"(v0));
  float h0 = __uint_as_float(hp<<16);
  float h1 = __uint_as_float(hp & 0xffff0000u);
  float l0 = v0 - h0, l1 = v1 - h1;
  asm("cvt.rn.bf16x2.f32 %0, %1, %2;" : "=r"(lp) : "f"(l1), "f"(l0));
}

#define MMA16816(d, a, b0, b1) \
  asm volatile("mma.sync.aligned.m16n8k16.row.col.f32.bf16.bf16.f32 " \
    "{%0,%1,%2,%3}, {%4,%5,%6,%7}, {%8,%9}, {%0,%1,%2,%3};" \
    : "+f"((d)[0]),"+f"((d)[1]),"+f"((d)[2]),"+f"((d)[3]) \
    : "r"((a)[0]),"r"((a)[1]),"r"((a)[2]),"r"((a)[3]), "r"(b0),"r"(b1))

#define REDADD(p, v) asm volatile("red.global.add.f32 [%0], %1;" :: "l"(p), "f"(v) : "memory")

__device__ __forceinline__ void aff_from_stats(const float* sS, const float* sQ,
                                               const float* gm, const float* bt,
                                               int c, float& a, float& cc){
  float mu = sS[c]*(1.f/(float)NHW);
  float var = sQ[c]*(1.f/(float)NHW) - mu*mu;
  a = gm[c]*rsqrtf(var+EPSV);
  cc = bt[c]-mu*a;
}

// ---------------- small kernels ----------------
__global__ void k_zero(){
  int t = blockIdx.x*512 + threadIdx.x;
  if(t < 768){ g_sS[t]=0.f; g_sQ[t]=0.f; }
  if(t < ND2){ g_accS[t]=0.f; g_accQ[t]=0.f; }
  if(t < CH*LDIM){ g_row[t]=0.f; g_col[t]=0.f; }
}

// merged front kernel: blocks [0,788) stats1d, [788,1628) stats2, [1628,2348) prepB
__global__ void k_front(const float* __restrict__ x1, const float* __restrict__ x2,
                        const float* __restrict__ rw){
  int b = blockIdx.x;
  int tid = threadIdx.x;
  if(b < 788){
    const float* p = x1 + b*LDIM;
    float s=0.f,q=0.f;
    for(int i=tid;i<LDIM;i+=256){ float v=p[i]; s+=v; q+=v*v; }
    __shared__ float ss[8], sq[8];
    s = wsum(s); q = wsum(q);
    int w = tid>>5, ln = tid&31;
    if(ln==0){ ss[w]=s; sq[w]=q; }
    __syncthreads();
    if(tid==0){
      float S=0.f,Q=0.f;
      #pragma unroll
      for(int i=0;i<8;i++){S+=ss[i];Q+=sq[i];}
      float mu=S/(float)LDIM; float var=Q/(float)LDIM-mu*mu;
      g_rs1[b]=rsqrtf(var+EPSV);
    }
  } else if(b < 1628){
    int i = b-788;
    int d = i>>2, seg = i&3;
    const float4* p = (const float4*)(x2 + d*NHW + seg*36864);
    float s=0.f,q=0.f;
    for(int i2=tid;i2<9216;i2+=256){
      float4 v=p[i2];
      s += v.x+v.y+v.z+v.w;
      q += v.x*v.x+v.y*v.y+v.z*v.z+v.w*v.w;
    }
    __shared__ float ss2[8], sq2[8];
    s=wsum(s); q=wsum(q);
    int w=tid>>5, ln=tid&31;
    if(ln==0){ ss2[w]=s; sq2[w]=q; }
    __syncthreads();
    if(tid==0){
      float S=0.f,Q=0.f;
      #pragma unroll
      for(int i2=0;i2<8;i2++){S+=ss2[i2];Q+=sq2[i2];}
      atomicAdd(&g_accS[d],S); atomicAdd(&g_accQ[d],Q);
    }
  } else {
    int idx = (b-1628)*256 + tid;
    if(idx >= 10*2*9*16*64) return;
    int n   = idx & 63;
    int cp  = (idx>>6) & 15;
    int tap = (idx>>10) % 9;
    int rest= (idx>>10) / 9;
    int half= rest & 1;
    int lk  = rest >> 1;
    int ci0 = half*32 + cp*2;
    float w0 = rw[((lk*CH + n)*CH + ci0  )*9 + tap];
    float w1 = rw[((lk*CH + n)*CH + ci0+1)*9 + tap];
    uint32_t hp, lp;
    bf16split2(w0, w1, hp, lp);
    int o = ((rest*9 + tap)*16 + cp)*72 + n;
    g_wBh[o] = hp; g_wBl[o] = lp;
  }
}

// merged weight fold (rs2 computed inline from accumulated stats)
__global__ void k_fold(const float* __restrict__ W1, const float* __restrict__ W2){
  int idx = blockIdx.x*256+threadIdx.x;
  if(idx < CH*ND1){
    int c = idx/ND1, d = idx%ND1;
    float rs = g_rs1[d];
    g_W1af[idx] = W1[c*2*ND1 + d]*rs;
    g_W1bf[idx] = W1[c*2*ND1 + ND1 + d]*rs;
  } else {
    int i2 = idx - CH*ND1;
    if(i2 < CH*ND2){
      int d = i2%ND2;
      float mu = g_accS[d]*(1.f/(float)NHW);
      float var = g_accQ[d]*(1.f/(float)NHW) - mu*mu;
      g_W2f[i2] = W2[i2]*rsqrtf(var+EPSV);
    }
  }
}

// rowcol: grid (64 c, 4 segs), 384 threads; unroll-2 dual accumulators; atomic combine
__global__ void k_rowcol(const float* __restrict__ x1){
  int c = blockIdx.x, seg = blockIdx.y, i = threadIdx.x;
  const float* wa = g_W1af + c*ND1;
  const float* wb = g_W1bf + c*ND1;
  int d0 = seg*197;
  int d1 = (seg==3) ? ND1 : (d0+197);
  float r0=0.f,r1=0.f,c0=0.f,c1=0.f;
  int d=d0;
  for(; d+1<d1; d+=2){
    float va = x1[d*LDIM + i];
    float vb = x1[(d+1)*LDIM + i];
    r0 += wa[d]*va;   c0 += wb[d]*va;
    r1 += wa[d+1]*vb; c1 += wb[d+1]*vb;
  }
  if(d<d1){ float v=x1[d*LDIM+i]; r0+=wa[d]*v; c0+=wb[d]*v; }
  atomicAdd(&g_row[c*LDIM+i], r0+r1);
  atomicAdd(&g_col[c*LDIM+i], c0+c1);
}

// rc stats -> a1/c1
__global__ void k_rcstats(const float* __restrict__ g1, const float* __restrict__ b1){
  int c = blockIdx.x;
  float sr=0.f,qr=0.f,sc=0.f,qc=0.f;
  for(int i=threadIdx.x;i<LDIM;i+=128){
    float r=g_row[c*LDIM+i], cl=g_col[c*LDIM+i];
    sr+=r; qr+=r*r; sc+=cl; qc+=cl*cl;
  }
  __shared__ float sm4[4][4];
  sr=wsum(sr); qr=wsum(qr); sc=wsum(sc); qc=wsum(qc);
  int w=threadIdx.x>>5, ln=threadIdx.x&31;
  if(ln==0){ sm4[w][0]=sr; sm4[w][1]=qr; sm4[w][2]=sc; sm4[w][3]=qc; }
  __syncthreads();
  if(threadIdx.x==0){
    float Sr=0.f,Qr=0.f,Sc=0.f,Qc=0.f;
    #pragma unroll
    for(int i=0;i<4;i++){Sr+=sm4[i][0];Qr+=sm4[i][1];Sc+=sm4[i][2];Qc+=sm4[i][3];}
    float mr=Sr/(float)LDIM, mc=Sc/(float)LDIM;
    float vr=Qr/(float)LDIM-mr*mr, vc=Qc/(float)LDIM-mc*mc;
    float rs=rsqrtf(vr+vc+EPSV);
    float a=g1[c]*rs;
    g_a1[c]=a; g_c1[c]=b1[c]-(mr+mc)*a;
  }
}

// pair2 GEMM with packed f32x2
__global__ void k_pair2(const float* __restrict__ x2){
  extern __shared__ float sm[];
  float* W2T = sm;            // [d][c] 210*64
  float* xs  = sm + 13440;    // 6*256
  int tid=threadIdx.x;
  for(int i=tid;i<13440;i+=256){ int d=i>>6, c=i&63; W2T[i]=g_W2f[c*ND2+d]; }
  int cg = tid>>7, pxl = tid&127;
  int pix0 = blockIdx.x*256;
  unsigned long long a0[16], a1[16];
  #pragma unroll
  for(int p=0;p<16;p++){ a0[p]=0ULL; a1[p]=0ULL; }
  __syncthreads();
  for(int d0=0; d0<ND2; d0+=6){
    for(int i=tid;i<384;i+=256)
      ((float4*)xs)[i] = ((const float4*)(x2 + (d0 + (i>>6))*NHW + pix0))[i&63];
    __syncthreads();
    #pragma unroll
    for(int dd=0;dd<6;dd++){
      float2 v = *(const float2*)(xs + dd*256 + pxl*2);
      unsigned long long dv0, dv1;
      asm("mov.b64 %0, {%1,%1};" : "=l"(dv0) : "f"(v.x));
      asm("mov.b64 %0, {%1,%1};" : "=l"(dv1) : "f"(v.y));
      const unsigned long long* wp = (const unsigned long long*)(W2T + (d0+dd)*64 + cg*32);
      #pragma unroll
      for(int p=0;p<16;p++){
        unsigned long long w2 = wp[p];
        asm("fma.rn.f32x2 %0, %1, %2, %0;" : "+l"(a0[p]) : "l"(w2), "l"(dv0));
        asm("fma.rn.f32x2 %0, %1, %2, %0;" : "+l"(a1[p]) : "l"(w2), "l"(dv1));
      }
    }
    __syncthreads();
  }
  int P = pix0 + pxl*2;
  #pragma unroll
  for(int p=0;p<16;p++){
    float l0,h0,l1,h1;
    asm("mov.b64 {%0,%1}, %2;" : "=f"(l0), "=f"(h0) : "l"(a0[p]));
    asm("mov.b64 {%0,%1}, %2;" : "=f"(l1), "=f"(h1) : "l"(a1[p]));
    int c = cg*32 + 2*p;
    g_bufU[c*NHW + P]       = l0;
    g_bufU[c*NHW + P + 1]   = l1;
    g_bufU[(c+1)*NHW + P]   = h0;
    g_bufU[(c+1)*NHW + P+1] = h1;
  }
}

// per-channel sum/sumsq accumulate into a stat set (float4)
__global__ void k_cstats(const float* __restrict__ buf, float* __restrict__ sS, float* __restrict__ sQ){
  int c=blockIdx.x, seg=blockIdx.y;
  const float4* p = (const float4*)(buf + c*NHW + seg*18432);
  float s=0.f,q=0.f;
  for(int i=threadIdx.x;i<4608;i+=256){
    float4 v=p[i];
    s += v.x+v.y+v.z+v.w;
    q += v.x*v.x+v.y*v.y+v.z*v.z+v.w*v.w;
  }
  __shared__ float ss[8], sq[8];
  s=wsum(s); q=wsum(q);
  int w=threadIdx.x>>5, ln=threadIdx.x&31;
  if(ln==0){ ss[w]=s; sq[w]=q; }
  __syncthreads();
  if(threadIdx.x==0){
    float S=0.f,Q=0.f;
    #pragma unroll
    for(int i=0;i<8;i++){S+=ss[i];Q+=sq[i];}
    atomicAdd(&sS[c],S); atomicAdd(&sQ[c],Q);
  }
}

// pair stage, f32x2 (a2/c2 computed inline from stat set 0)
__global__ void k_pair(const float* __restrict__ W3,
                       const float* __restrict__ g2, const float* __restrict__ b2){
  extern __shared__ float sm[];
  float* WaT = sm;             // [d][c] stride 66
  float* WbT = sm + 64*66;
  float* p1s = sm + 2*64*66;
  float* p2s = p1s + 4096;
  float* aS2 = p2s + 4096;     // 64
  float* cS2 = aS2 + 64;       // 64
  int tid=threadIdx.x;
  for(int i=tid;i<4096;i+=256){
    int d=i&63, c=i>>6;
    WaT[d*66+c]=W3[c*128+d];
    WbT[d*66+c]=W3[c*128+64+d];
  }
  if(tid<64){ float a,cc; aff_from_stats(g_sS, g_sQ, g2, b2, tid, a, cc); aS2[tid]=a; cS2[tid]=cc; }
  __syncthreads();
  int P0 = blockIdx.x*64;
  int i0 = P0/LDIM, j0 = P0 - i0*LDIM;
  for(int idx=tid;idx<4096;idx+=256){
    int c=idx>>6, px=idx&63;
    float v1 = g_row[c*LDIM+i0] + g_col[c*LDIM+j0+px];
    p1s[idx] = lrelu(g_a1[c]*v1 + g_c1[c]);
    float u = g_bufU[c*NHW + P0 + px];
    p2s[idx] = lrelu(aS2[c]*u + cS2[c]);
  }
  __syncthreads();
  int pi=tid&31, cg=tid>>5;
  unsigned long long acc[8];
  #pragma unroll
  for(int p=0;p<8;p++) acc[p]=0ULL;
  for(int dd=0;dd<64;dd++){
    float2 v1 = *(const float2*)(p1s + dd*64 + pi*2);
    float2 v2 = *(const float2*)(p2s + dd*64 + pi*2);
    unsigned long long s10,s11,s20,s21;
    asm("mov.b64 %0, {%1,%1};" : "=l"(s10) : "f"(v1.x));
    asm("mov.b64 %0, {%1,%1};" : "=l"(s11) : "f"(v1.y));
    asm("mov.b64 %0, {%1,%1};" : "=l"(s20) : "f"(v2.x));
    asm("mov.b64 %0, {%1,%1};" : "=l"(s21) : "f"(v2.y));
    const unsigned long long* wa = (const unsigned long long*)(WaT + dd*66 + cg*8);
    const unsigned long long* wb = (const unsigned long long*)(WbT + dd*66 + cg*8);
    #pragma unroll
    for(int p=0;p<4;p++){
      unsigned long long wA=wa[p], wB=wb[p];
      asm("fma.rn.f32x2 %0, %1, %2, %0;" : "+l"(acc[p*2  ]) : "l"(wA), "l"(s10));
      asm("fma.rn.f32x2 %0, %1, %2, %0;" : "+l"(acc[p*2  ]) : "l"(wB), "l"(s20));
      asm("fma.rn.f32x2 %0, %1, %2, %0;" : "+l"(acc[p*2+1]) : "l"(wA), "l"(s11));
      asm("fma.rn.f32x2 %0, %1, %2, %0;" : "+l"(acc[p*2+1]) : "l"(wB), "l"(s21));
    }
  }
  #pragma unroll
  for(int p=0;p<4;p++){
    #pragma unroll
    for(int q=0;q<2;q++){
      float lo,hi;
      asm("mov.b64 {%0,%1}, %2;" : "=f"(lo), "=f"(hi) : "l"(acc[p*2+q]));
      int c = cg*8 + 2*p;
      int P = P0 + pi*2 + q;
      g_bufX[c*NHW + P]     = lo;
      g_bufX[(c+1)*NHW + P] = hi;
    }
  }
}

__global__ void k_apply_res(const float* __restrict__ u, const float* __restrict__ res,
                            float* __restrict__ o,
                            const float* __restrict__ sS, const float* __restrict__ sQ,
                            const float* __restrict__ gm, const float* __restrict__ bt){
  int c=blockIdx.y;
  float a,cc; aff_from_stats(sS,sQ,gm,bt,c,a,cc);
  int idx = blockIdx.x*256 + threadIdx.x;
  float4 uv = ((const float4*)(u + c*NHW))[idx];
  float4 rv = ((const float4*)(res + c*NHW))[idx];
  float4 ov;
  ov.x = lrelu(a*uv.x+cc)+rv.x; ov.y = lrelu(a*uv.y+cc)+rv.y;
  ov.z = lrelu(a*uv.z+cc)+rv.z; ov.w = lrelu(a*uv.w+cc)+rv.w;
  ((float4*)(o + c*NHW))[idx] = ov;
}

// ---------------- conv 3x3 dilated 64->64 via mma.sync bf16 hi/lo split ----------------
// 256 threads, 8 warps, occ 2. Fused per-channel stat accumulation in epilogue.
template<int D>
__global__ void __launch_bounds__(256,2)
k_convM(const float* __restrict__ in, float* __restrict__ out,
        const uint32_t* __restrict__ wBh, const uint32_t* __restrict__ wBl,
        const float* __restrict__ sSi, const float* __restrict__ sQi,
        const float* __restrict__ gm,  const float* __restrict__ bt,
        float* __restrict__ sSo, float* __restrict__ sQo,
        const float* __restrict__ resIn, float* __restrict__ resOut){
  constexpr int TW2  = 16+2*D;
  constexpr int PLHW = (D==1)?328:((D==2)?424:584);
  constexpr int TILE_W = 16*PLHW;
  extern __shared__ uint32_t smu[];
  uint32_t* tileH = smu;
  uint32_t* tileL = smu + TILE_W;
  uint32_t* Bh    = smu + 2*TILE_W;     // 2 x 1152
  uint32_t* Bl    = Bh + 2*1152;        // 2 x 1152
  float* aS = (float*)(Bl + 2*1152);    // 64
  float* cS = aS + 64;                  // 64
  float* red = cS + 64;                 // 512

  int tid = threadIdx.x;
  int lane = tid & 31, wid = tid >> 5;
  int wm = wid >> 1, wn = wid & 1;
  int g = lane >> 2, tig = lane & 3;
  int x0 = blockIdx.x*16, y0 = blockIdx.y*16;

  bool doAct = (gm != nullptr);
  bool hasRes = (resIn != nullptr);
  bool wAct = (resOut != nullptr);
  if(tid < 64){
    if(doAct){ float a,cc; aff_from_stats(sSi,sQi,gm,bt,tid,a,cc); aS[tid]=a; cS[tid]=cc; }
    else { aS[tid]=1.f; cS[tid]=0.f; }
  }

  float acc[4][4][4];
  #pragma unroll
  for(int j=0;j<4;j++)
    #pragma unroll
    for(int na=0;na<4;na++)
      #pragma unroll
      for(int q=0;q<4;q++) acc[j][na][q]=0.f;

  for(int half=0; half<2; half++){
    __syncthreads();
    for(int idx=tid; idx<16*TW2*TW2; idx+=256){
      int cp = idx/(TW2*TW2); int rr = idx - cp*(TW2*TW2);
      int r = rr/TW2, c2 = rr - r*TW2;
      int gy = y0 - D + r, gx = x0 - D + c2;
      float v0=0.f, v1=0.f;
      if(((unsigned)gy<384u) && ((unsigned)gx<384u)){
        int ci0 = half*32 + cp*2;
        int off0 = ci0*NHW + gy*LDIM + gx;
        float u0 = in[off0], u1 = in[off0+NHW];
        if(hasRes){
          float t0 = aS[ci0]*u0 + cS[ci0];
          float t1 = aS[ci0+1]*u1 + cS[ci0+1];
          v0 = fmaxf(t0, 0.01f*t0) + resIn[off0];
          v1 = fmaxf(t1, 0.01f*t1) + resIn[off0+NHW];
          if((unsigned)(gy-y0)<16u && (unsigned)(gx-x0)<16u){
            resOut[off0] = v0; resOut[off0+NHW] = v1;
          }
        } else if(doAct){
          float t0 = aS[ci0]*u0 + cS[ci0];     v0 = fmaxf(t0, 0.01f*t0);
          float t1 = aS[ci0+1]*u1 + cS[ci0+1]; v1 = fmaxf(t1, 0.01f*t1);
          if(wAct && (unsigned)(gy-y0)<16u && (unsigned)(gx-x0)<16u){
            resOut[off0] = v0; resOut[off0+NHW] = v1;
          }
        } else { v0=u0; v1=u1; }
      }
      uint32_t hp, lp;
      bf16split2(v0, v1, hp, lp);
      int off = cp*PLHW + r*TW2 + c2;
      tileH[off] = hp; tileL[off] = lp;
    }
    const uint4* bsrcH = (const uint4*)(wBh + (half*9)*1152);
    const uint4* bsrcL = (const uint4*)(wBl + (half*9)*1152);
    for(int i=tid;i<288;i+=256){ ((uint4*)Bh)[i]=bsrcH[i]; ((uint4*)Bl)[i]=bsrcL[i]; }
    __syncthreads();

    for(int tap=0; tap<9; tap++){
      int buf = tap & 1;
      if(tap < 8){
        const uint4* nh = bsrcH + (tap+1)*288;
        const uint4* nl = bsrcL + (tap+1)*288;
        uint4* dh = (uint4*)(Bh + (buf^1)*1152);
        uint4* dl = (uint4*)(Bl + (buf^1)*1152);
        for(int i=tid;i<288;i+=256){ dh[i]=nh[i]; dl[i]=nl[i]; }
      }
      int ky = tap/3, kx = tap - ky*3;
      #pragma unroll
      for(int kc=0;kc<2;kc++){
        uint32_t AH[4][4], AL[4][4];
        const uint32_t* tb = tileH + (kc*8+tig)*PLHW + (ky*D)*TW2 + kx*D + g;
        #pragma unroll
        for(int j=0;j<4;j++){
          const uint32_t* th = tb + (wm*4+j)*TW2;
          AH[j][0]=th[0]; AH[j][1]=th[8]; AH[j][2]=th[4*PLHW]; AH[j][3]=th[4*PLHW+8];
          const uint32_t* tl = th + TILE_W;
          AL[j][0]=tl[0]; AL[j][1]=tl[8]; AL[j][2]=tl[4*PLHW]; AL[j][3]=tl[4*PLHW+8];
        }
        const uint32_t* bbh = Bh + buf*1152 + (kc*8+tig)*72 + wn*32 + g;
        const uint32_t* bbl = Bl + buf*1152 + (kc*8+tig)*72 + wn*32 + g;
        #pragma unroll
        for(int na=0;na<4;na++){
          uint32_t bh0 = bbh[na*8], bh1 = bbh[na*8 + 4*72];
          uint32_t bl0 = bbl[na*8], bl1 = bbl[na*8 + 4*72];
          #pragma unroll
          for(int j=0;j<4;j++) MMA16816(acc[j][na], AH[j], bh0, bh1);
          #pragma unroll
          for(int j=0;j<4;j++) MMA16816(acc[j][na], AH[j], bl0, bl1);
          #pragma unroll
          for(int j=0;j<4;j++) MMA16816(acc[j][na], AL[j], bh0, bh1);
        }
      }
      __syncthreads();
    }
  }
  // epilogue: write output
  #pragma unroll
  for(int j=0;j<4;j++){
    int gy = y0 + wm*4 + j;
    #pragma unroll
    for(int na=0;na<4;na++){
      int co = wn*32 + na*8 + tig*2;
      float* op = out + co*NHW + gy*LDIM + x0;
      op[g]         = acc[j][na][0];
      op[NHW + g]   = acc[j][na][1];
      op[g+8]       = acc[j][na][2];
      op[NHW + g+8] = acc[j][na][3];
    }
  }
  // fused per-channel stats
  float sv[16];
  #pragma unroll
  for(int na=0;na<4;na++){
    #pragma unroll
    for(int par=0;par<2;par++){
      float s=0.f, q=0.f;
      #pragma unroll
      for(int j=0;j<4;j++){
        float v0=acc[j][na][par], v1=acc[j][na][par+2];
        s += v0+v1; q += v0*v0+v1*v1;
      }
      sv[(na*2+par)*2]   = s;
      sv[(na*2+par)*2+1] = q;
    }
  }
  #pragma unroll
  for(int off=4; off<32; off<<=1){
    #pragma unroll
    for(int i=0;i<16;i++) sv[i] += __shfl_xor_sync(0xffffffffu, sv[i], off);
  }
  if(lane<4){
    #pragma unroll
    for(int i=0;i<16;i++) red[wid*64 + lane*16 + i] = sv[i];
  }
  __syncthreads();
  if(tid<128){
    int sq = tid>>6, ch = tid&63;
    int wn_=ch>>5, na_=(ch>>3)&3, tg=(ch>>1)&3, par=ch&1;
    float tot=0.f;
    #pragma unroll
    for(int k=0;k<4;k++) tot += red[(2*k+wn_)*64 + tg*16 + (na_*2+par)*2 + sq];
    REDADD((sq? sQo : sSo)+ch, tot);
  }
}

// ---------------- host ----------------
static void launch_conv(int d, const float* in, float* out,
                        const uint32_t* wh, const uint32_t* wl,
                        const float* sSi, const float* sQi,
                        const float* gm, const float* bt,
                        float* sSo, float* sQo,
                        const float* resIn, float* resOut){
  dim3 g(24,24);
  if(d==1)      k_convM<1><<<g,256,62976>>>(in,out,wh,wl,sSi,sQi,gm,bt,sSo,sQo,resIn,resOut);
  else if(d==2) k_convM<2><<<g,256,75264>>>(in,out,wh,wl,sSi,sQi,gm,bt,sSo,sQo,resIn,resOut);
  else          k_convM<4><<<g,256,95744>>>(in,out,wh,wl,sSi,sQi,gm,bt,sSo,sQo,resIn,resOut);
}

extern "C" void kernel_launch(void* const* d_in, const int* in_sizes, int n_in,
                              void* d_out, int out_size){
  const float* x1 =(const float*)d_in[0];
  const float* x2 =(const float*)d_in[1];
  const float* W1 =(const float*)d_in[2];
  const float* g1 =(const float*)d_in[3];
  const float* b1 =(const float*)d_in[4];
  const float* W2 =(const float*)d_in[5];
  const float* g2 =(const float*)d_in[6];
  const float* b2 =(const float*)d_in[7];
  const float* W3 =(const float*)d_in[8];
  const float* g3 =(const float*)d_in[9];
  const float* b3 =(const float*)d_in[10];
  const float* rw =(const float*)d_in[11];
  const float* rg =(const float*)d_in[13];
  const float* rbe=(const float*)d_in[14];
  float* outp=(float*)d_out;

  float *bufT,*bufU,*bufX,*bufV,*sS,*sQ;
  uint32_t *wBh,*wBl;
  cudaGetSymbolAddress((void**)&bufT, g_bufT);
  cudaGetSymbolAddress((void**)&bufU, g_bufU);
  cudaGetSymbolAddress((void**)&bufX, g_bufX);
  cudaGetSymbolAddress((void**)&bufV, g_bufV);
  cudaGetSymbolAddress((void**)&wBh,  g_wBh);
  cudaGetSymbolAddress((void**)&wBl,  g_wBl);
  cudaGetSymbolAddress((void**)&sS,   g_sS);
  cudaGetSymbolAddress((void**)&sQ,   g_sQ);

  cudaFuncSetAttribute(k_convM<1>, cudaFuncAttributeMaxDynamicSharedMemorySize, 62976);
  cudaFuncSetAttribute(k_convM<2>, cudaFuncAttributeMaxDynamicSharedMemorySize, 75264);
  cudaFuncSetAttribute(k_convM<4>, cudaFuncAttributeMaxDynamicSharedMemorySize, 95744);
  cudaFuncSetAttribute(k_pair2,    cudaFuncAttributeMaxDynamicSharedMemorySize, 61440);
  cudaFuncSetAttribute(k_pair,     cudaFuncAttributeMaxDynamicSharedMemorySize, 67584);

  k_zero<<<48,512>>>();
  k_front<<<2348,256>>>(x1, x2, rw);
  k_fold<<<(CH*ND1+CH*ND2+255)/256,256>>>(W1, W2);
  k_rowcol<<<dim3(64,4),384>>>(x1);
  k_rcstats<<<64,128>>>(g1,b1);
  k_pair2<<<576,256,61440>>>(x2);
  k_cstats<<<dim3(64,8),256>>>(bufU, sS+0*64, sQ+0*64);       // set 0: pair2 out
  k_pair<<<2304,256,67584>>>(W3, g2, b2);                      // uses set 0
  k_cstats<<<dim3(64,8),256>>>(bufX, sS+1*64, sQ+1*64);       // set 1: pair out (raw)

  const int dil[5]={1,2,4,2,1};
  float* resBuf[2] = {bufV, bufX};
  int cur = 0;   // bufV will hold the activated pair output (residual) after conv1-l0
  for(int l=0;l<5;l++){
    int d=dil[l];
    const uint32_t* wh0 = wBh + (l*2  )*20736;
    const uint32_t* wl0 = wBl + (l*2  )*20736;
    const uint32_t* wh1 = wBh + (l*2+1)*20736;
    const uint32_t* wl1 = wBl + (l*2+1)*20736;
    float* s0S = sS + (2+2*l)*64;  float* s0Q = sQ + (2+2*l)*64;
    float* s1S = sS + (3+2*l)*64;  float* s1Q = sQ + (3+2*l)*64;
    if(l==0){
      launch_conv(d, bufX, bufT, wh0, wl0,
                  sS+1*64, sQ+1*64, g3, b3, s0S, s0Q, nullptr, bufV);
    } else {
      float* sPS = sS + (1+2*l)*64;  float* sPQ = sQ + (1+2*l)*64;
      launch_conv(d, bufU, bufT, wh0, wl0,
                  sPS, sPQ, rg+(2*l-1)*CH, rbe+(2*l-1)*CH, s0S, s0Q,
                  resBuf[cur], resBuf[cur^1]);
      cur ^= 1;
    }
    launch_conv(d, bufT, bufU, wh1, wl1,
                s0S, s0Q, rg+(2*l)*CH, rbe+(2*l)*CH, s1S, s1Q, nullptr,nullptr);
  }
  k_apply_res<<<dim3(144,64),256>>>(bufU, resBuf[cur], outp,
                                    sS+11*64, sQ+11*64, rg+9*CH, rbe+9*CH);
}

// round 15
// speedup vs baseline: 1.0646x; 1.0250x over previous
#include <cuda_runtime.h>
#include <cstdint>

constexpr int LDIM = 384;
constexpr int NHW  = 147456;   // 384*384
constexpr int CH   = 64;
constexpr int ND1  = 788;
constexpr int ND2  = 210;
#define EPSV 1e-5f

// ---------------- device scratch (static, no allocations) ----------------
__device__ float g_bufT[CH*NHW];
__device__ float g_bufU[CH*NHW];
__device__ float g_bufX[CH*NHW];
__device__ float g_bufV[CH*NHW];   // residual ping-pong partner of bufX
__device__ float g_rs1[ND1];
__device__ float g_W1af[CH*ND1];
__device__ float g_W1bf[CH*ND1];
__device__ float g_W2f[CH*ND2];
__device__ float g_row[CH*LDIM];
__device__ float g_col[CH*LDIM];
__device__ float g_a1[CH], g_c1[CH];
__device__ float g_accS[ND2], g_accQ[ND2];
// 12 per-channel stat sets (sum / sumsq), each written once per run
__device__ float g_sS[12*64];
__device__ float g_sQ[12*64];
// conv weights as B-fragment words: [lk][half][tap][cipair 16][72 (64 used)]
__device__ uint32_t g_wBh[10*2*9*16*72];
__device__ uint32_t g_wBl[10*2*9*16*72];

__device__ __forceinline__ float lrelu(float v){ return fmaxf(v, 0.01f*v); }

__device__ __forceinline__ float wsum(float v){
  #pragma unroll
  for(int o=16;o>0;o>>=1) v += __shfl_down_sync(0xffffffffu, v, o);
  return v;
}

__device__ __forceinline__ void bf16split2(float v0, float v1, uint32_t& hp, uint32_t& lp){
  asm("cvt.rn.bf16x2.f32 %0, %1, %2;" : "=r"(hp) : "f"(v1), "f"(v0));
  float h0 = __uint_as_float(hp<<16);
  float h1 = __uint_as_float(hp & 0xffff0000u);
  float l0 = v0 - h0, l1 = v1 - h1;
  asm("cvt.rn.bf16x2.f32 %0, %1, %2;" : "=r"(lp) : "f"(l1), "f"(l0));
}

#define MMA16816(d, a, b0, b1) \
  asm volatile("mma.sync.aligned.m16n8k16.row.col.f32.bf16.bf16.f32 " \
    "{%0,%1,%2,%3}, {%4,%5,%6,%7}, {%8,%9}, {%0,%1,%2,%3};" \
    : "+f"((d)[0]),"+f"((d)[1]),"+f"((d)[2]),"+f"((d)[3]) \
    : "r"((a)[0]),"r"((a)[1]),"r"((a)[2]),"r"((a)[3]), "r"(b0),"r"(b1))

#define REDADD(p, v) asm volatile("red.global.add.f32 [%0], %1;" :: "l"(p), "f"(v) : "memory")

__device__ __forceinline__ void aff_from_stats(const float* sS, const float* sQ,
                                               const float* gm, const float* bt,
                                               int c, float& a, float& cc){
  float mu = sS[c]*(1.f/(float)NHW);
  float var = sQ[c]*(1.f/(float)NHW) - mu*mu;
  a = gm[c]*rsqrtf(var+EPSV);
  cc = bt[c]-mu*a;
}

// ---------------- small kernels ----------------
__global__ void k_zero(){
  int t = blockIdx.x*512 + threadIdx.x;
  if(t < 768){ g_sS[t]=0.f; g_sQ[t]=0.f; }
  if(t < ND2){ g_accS[t]=0.f; g_accQ[t]=0.f; }
  if(t < CH*LDIM){ g_row[t]=0.f; g_col[t]=0.f; }
}

// merged front kernel: blocks [0,788) stats1d, [788,1628) stats2, [1628,2348) prepB
__global__ void k_front(const float* __restrict__ x1, const float* __restrict__ x2,
                        const float* __restrict__ rw){
  int b = blockIdx.x;
  int tid = threadIdx.x;
  if(b < 788){
    const float* p = x1 + b*LDIM;
    float s=0.f,q=0.f;
    for(int i=tid;i<LDIM;i+=256){ float v=p[i]; s+=v; q+=v*v; }
    __shared__ float ss[8], sq[8];
    s = wsum(s); q = wsum(q);
    int w = tid>>5, ln = tid&31;
    if(ln==0){ ss[w]=s; sq[w]=q; }
    __syncthreads();
    if(tid==0){
      float S=0.f,Q=0.f;
      #pragma unroll
      for(int i=0;i<8;i++){S+=ss[i];Q+=sq[i];}
      float mu=S/(float)LDIM; float var=Q/(float)LDIM-mu*mu;
      g_rs1[b]=rsqrtf(var+EPSV);
    }
  } else if(b < 1628){
    int i = b-788;
    int d = i>>2, seg = i&3;
    const float4* p = (const float4*)(x2 + d*NHW + seg*36864);
    float s=0.f,q=0.f;
    for(int i2=tid;i2<9216;i2+=256){
      float4 v=p[i2];
      s += v.x+v.y+v.z+v.w;
      q += v.x*v.x+v.y*v.y+v.z*v.z+v.w*v.w;
    }
    __shared__ float ss2[8], sq2[8];
    s=wsum(s); q=wsum(q);
    int w=tid>>5, ln=tid&31;
    if(ln==0){ ss2[w]=s; sq2[w]=q; }
    __syncthreads();
    if(tid==0){
      float S=0.f,Q=0.f;
      #pragma unroll
      for(int i2=0;i2<8;i2++){S+=ss2[i2];Q+=sq2[i2];}
      atomicAdd(&g_accS[d],S); atomicAdd(&g_accQ[d],Q);
    }
  } else {
    int idx = (b-1628)*256 + tid;
    if(idx >= 10*2*9*16*64) return;
    int n   = idx & 63;
    int cp  = (idx>>6) & 15;
    int tap = (idx>>10) % 9;
    int rest= (idx>>10) / 9;
    int half= rest & 1;
    int lk  = rest >> 1;
    int ci0 = half*32 + cp*2;
    float w0 = rw[((lk*CH + n)*CH + ci0  )*9 + tap];
    float w1 = rw[((lk*CH + n)*CH + ci0+1)*9 + tap];
    uint32_t hp, lp;
    bf16split2(w0, w1, hp, lp);
    int o = ((rest*9 + tap)*16 + cp)*72 + n;
    g_wBh[o] = hp; g_wBl[o] = lp;
  }
}

// merged weight fold (rs2 computed inline from accumulated stats)
__global__ void k_fold(const float* __restrict__ W1, const float* __restrict__ W2){
  int idx = blockIdx.x*256+threadIdx.x;
  if(idx < CH*ND1){
    int c = idx/ND1, d = idx%ND1;
    float rs = g_rs1[d];
    g_W1af[idx] = W1[c*2*ND1 + d]*rs;
    g_W1bf[idx] = W1[c*2*ND1 + ND1 + d]*rs;
  } else {
    int i2 = idx - CH*ND1;
    if(i2 < CH*ND2){
      int d = i2%ND2;
      float mu = g_accS[d]*(1.f/(float)NHW);
      float var = g_accQ[d]*(1.f/(float)NHW) - mu*mu;
      g_W2f[i2] = W2[i2]*rsqrtf(var+EPSV);
    }
  }
}

// rowcol: grid (64 c, 8 segs), 384 threads; 4-way unrolled accumulators; atomic combine
__global__ void k_rowcol(const float* __restrict__ x1){
  int c = blockIdx.x, seg = blockIdx.y, i = threadIdx.x;
  const float* wa = g_W1af + c*ND1;
  const float* wb = g_W1bf + c*ND1;
  int d0 = seg*99;
  int d1 = d0+99; if(d1 > ND1) d1 = ND1;
  float r0=0.f,r1=0.f,r2=0.f,r3=0.f,c0=0.f,c1=0.f,c2=0.f,c3=0.f;
  int d=d0;
  for(; d+3<d1; d+=4){
    float va = x1[d*LDIM + i];
    float vb = x1[(d+1)*LDIM + i];
    float vc = x1[(d+2)*LDIM + i];
    float vd = x1[(d+3)*LDIM + i];
    r0 += wa[d]*va;   c0 += wb[d]*va;
    r1 += wa[d+1]*vb; c1 += wb[d+1]*vb;
    r2 += wa[d+2]*vc; c2 += wb[d+2]*vc;
    r3 += wa[d+3]*vd; c3 += wb[d+3]*vd;
  }
  for(; d<d1; d++){ float v=x1[d*LDIM+i]; r0+=wa[d]*v; c0+=wb[d]*v; }
  atomicAdd(&g_row[c*LDIM+i], (r0+r1)+(r2+r3));
  atomicAdd(&g_col[c*LDIM+i], (c0+c1)+(c2+c3));
}

// rc stats -> a1/c1
__global__ void k_rcstats(const float* __restrict__ g1, const float* __restrict__ b1){
  int c = blockIdx.x;
  float sr=0.f,qr=0.f,sc=0.f,qc=0.f;
  for(int i=threadIdx.x;i<LDIM;i+=128){
    float r=g_row[c*LDIM+i], cl=g_col[c*LDIM+i];
    sr+=r; qr+=r*r; sc+=cl; qc+=cl*cl;
  }
  __shared__ float sm4[4][4];
  sr=wsum(sr); qr=wsum(qr); sc=wsum(sc); qc=wsum(qc);
  int w=threadIdx.x>>5, ln=threadIdx.x&31;
  if(ln==0){ sm4[w][0]=sr; sm4[w][1]=qr; sm4[w][2]=sc; sm4[w][3]=qc; }
  __syncthreads();
  if(threadIdx.x==0){
    float Sr=0.f,Qr=0.f,Sc=0.f,Qc=0.f;
    #pragma unroll
    for(int i=0;i<4;i++){Sr+=sm4[i][0];Qr+=sm4[i][1];Sc+=sm4[i][2];Qc+=sm4[i][3];}
    float mr=Sr/(float)LDIM, mc=Sc/(float)LDIM;
    float vr=Qr/(float)LDIM-mr*mr, vc=Qc/(float)LDIM-mc*mc;
    float rs=rsqrtf(vr+vc+EPSV);
    float a=g1[c]*rs;
    g_a1[c]=a; g_c1[c]=b1[c]-(mr+mc)*a;
  }
}

// pair2 GEMM with packed f32x2
__global__ void k_pair2(const float* __restrict__ x2){
  extern __shared__ float sm[];
  float* W2T = sm;            // [d][c] 210*64
  float* xs  = sm + 13440;    // 6*256
  int tid=threadIdx.x;
  for(int i=tid;i<13440;i+=256){ int d=i>>6, c=i&63; W2T[i]=g_W2f[c*ND2+d]; }
  int cg = tid>>7, pxl = tid&127;
  int pix0 = blockIdx.x*256;
  unsigned long long a0[16], a1[16];
  #pragma unroll
  for(int p=0;p<16;p++){ a0[p]=0ULL; a1[p]=0ULL; }
  __syncthreads();
  for(int d0=0; d0<ND2; d0+=6){
    for(int i=tid;i<384;i+=256)
      ((float4*)xs)[i] = ((const float4*)(x2 + (d0 + (i>>6))*NHW + pix0))[i&63];
    __syncthreads();
    #pragma unroll
    for(int dd=0;dd<6;dd++){
      float2 v = *(const float2*)(xs + dd*256 + pxl*2);
      unsigned long long dv0, dv1;
      asm("mov.b64 %0, {%1,%1};" : "=l"(dv0) : "f"(v.x));
      asm("mov.b64 %0, {%1,%1};" : "=l"(dv1) : "f"(v.y));
      const unsigned long long* wp = (const unsigned long long*)(W2T + (d0+dd)*64 + cg*32);
      #pragma unroll
      for(int p=0;p<16;p++){
        unsigned long long w2 = wp[p];
        asm("fma.rn.f32x2 %0, %1, %2, %0;" : "+l"(a0[p]) : "l"(w2), "l"(dv0));
        asm("fma.rn.f32x2 %0, %1, %2, %0;" : "+l"(a1[p]) : "l"(w2), "l"(dv1));
      }
    }
    __syncthreads();
  }
  int P = pix0 + pxl*2;
  #pragma unroll
  for(int p=0;p<16;p++){
    float l0,h0,l1,h1;
    asm("mov.b64 {%0,%1}, %2;" : "=f"(l0), "=f"(h0) : "l"(a0[p]));
    asm("mov.b64 {%0,%1}, %2;" : "=f"(l1), "=f"(h1) : "l"(a1[p]));
    int c = cg*32 + 2*p;
    g_bufU[c*NHW + P]       = l0;
    g_bufU[c*NHW + P + 1]   = l1;
    g_bufU[(c+1)*NHW + P]   = h0;
    g_bufU[(c+1)*NHW + P+1] = h1;
  }
}

// per-channel sum/sumsq accumulate into a stat set (float4)
__global__ void k_cstats(const float* __restrict__ buf, float* __restrict__ sS, float* __restrict__ sQ){
  int c=blockIdx.x, seg=blockIdx.y;
  const float4* p = (const float4*)(buf + c*NHW + seg*18432);
  float s=0.f,q=0.f;
  for(int i=threadIdx.x;i<4608;i+=256){
    float4 v=p[i];
    s += v.x+v.y+v.z+v.w;
    q += v.x*v.x+v.y*v.y+v.z*v.z+v.w*v.w;
  }
  __shared__ float ss[8], sq[8];
  s=wsum(s); q=wsum(q);
  int w=threadIdx.x>>5, ln=threadIdx.x&31;
  if(ln==0){ ss[w]=s; sq[w]=q; }
  __syncthreads();
  if(threadIdx.x==0){
    float S=0.f,Q=0.f;
    #pragma unroll
    for(int i=0;i<8;i++){S+=ss[i];Q+=sq[i];}
    atomicAdd(&sS[c],S); atomicAdd(&sQ[c],Q);
  }
}

// pair stage, f32x2 (a2/c2 computed inline from stat set 0)
__global__ void k_pair(const float* __restrict__ W3,
                       const float* __restrict__ g2, const float* __restrict__ b2){
  extern __shared__ float sm[];
  float* WaT = sm;             // [d][c] stride 66
  float* WbT = sm + 64*66;
  float* p1s = sm + 2*64*66;
  float* p2s = p1s + 4096;
  float* aS2 = p2s + 4096;     // 64
  float* cS2 = aS2 + 64;       // 64
  int tid=threadIdx.x;
  for(int i=tid;i<4096;i+=256){
    int d=i&63, c=i>>6;
    WaT[d*66+c]=W3[c*128+d];
    WbT[d*66+c]=W3[c*128+64+d];
  }
  if(tid<64){ float a,cc; aff_from_stats(g_sS, g_sQ, g2, b2, tid, a, cc); aS2[tid]=a; cS2[tid]=cc; }
  __syncthreads();
  int P0 = blockIdx.x*64;
  int i0 = P0/LDIM, j0 = P0 - i0*LDIM;
  for(int idx=tid;idx<4096;idx+=256){
    int c=idx>>6, px=idx&63;
    float v1 = g_row[c*LDIM+i0] + g_col[c*LDIM+j0+px];
    p1s[idx] = lrelu(g_a1[c]*v1 + g_c1[c]);
    float u = g_bufU[c*NHW + P0 + px];
    p2s[idx] = lrelu(aS2[c]*u + cS2[c]);
  }
  __syncthreads();
  int pi=tid&31, cg=tid>>5;
  unsigned long long acc[8];
  #pragma unroll
  for(int p=0;p<8;p++) acc[p]=0ULL;
  for(int dd=0;dd<64;dd++){
    float2 v1 = *(const float2*)(p1s + dd*64 + pi*2);
    float2 v2 = *(const float2*)(p2s + dd*64 + pi*2);
    unsigned long long s10,s11,s20,s21;
    asm("mov.b64 %0, {%1,%1};" : "=l"(s10) : "f"(v1.x));
    asm("mov.b64 %0, {%1,%1};" : "=l"(s11) : "f"(v1.y));
    asm("mov.b64 %0, {%1,%1};" : "=l"(s20) : "f"(v2.x));
    asm("mov.b64 %0, {%1,%1};" : "=l"(s21) : "f"(v2.y));
    const unsigned long long* wa = (const unsigned long long*)(WaT + dd*66 + cg*8);
    const unsigned long long* wb = (const unsigned long long*)(WbT + dd*66 + cg*8);
    #pragma unroll
    for(int p=0;p<4;p++){
      unsigned long long wA=wa[p], wB=wb[p];
      asm("fma.rn.f32x2 %0, %1, %2, %0;" : "+l"(acc[p*2  ]) : "l"(wA), "l"(s10));
      asm("fma.rn.f32x2 %0, %1, %2, %0;" : "+l"(acc[p*2  ]) : "l"(wB), "l"(s20));
      asm("fma.rn.f32x2 %0, %1, %2, %0;" : "+l"(acc[p*2+1]) : "l"(wA), "l"(s11));
      asm("fma.rn.f32x2 %0, %1, %2, %0;" : "+l"(acc[p*2+1]) : "l"(wB), "l"(s21));
    }
  }
  #pragma unroll
  for(int p=0;p<4;p++){
    #pragma unroll
    for(int q=0;q<2;q++){
      float lo,hi;
      asm("mov.b64 {%0,%1}, %2;" : "=f"(lo), "=f"(hi) : "l"(acc[p*2+q]));
      int c = cg*8 + 2*p;
      int P = P0 + pi*2 + q;
      g_bufX[c*NHW + P]     = lo;
      g_bufX[(c+1)*NHW + P] = hi;
    }
  }
}

__global__ void k_apply_res(const float* __restrict__ u, const float* __restrict__ res,
                            float* __restrict__ o,
                            const float* __restrict__ sS, const float* __restrict__ sQ,
                            const float* __restrict__ gm, const float* __restrict__ bt){
  int c=blockIdx.y;
  float a,cc; aff_from_stats(sS,sQ,gm,bt,c,a,cc);
  int idx = blockIdx.x*256 + threadIdx.x;
  float4 uv = ((const float4*)(u + c*NHW))[idx];
  float4 rv = ((const float4*)(res + c*NHW))[idx];
  float4 ov;
  ov.x = lrelu(a*uv.x+cc)+rv.x; ov.y = lrelu(a*uv.y+cc)+rv.y;
  ov.z = lrelu(a*uv.z+cc)+rv.z; ov.w = lrelu(a*uv.w+cc)+rv.w;
  ((float4*)(o + c*NHW))[idx] = ov;
}

// ---------------- conv 3x3 dilated 64->64 via mma.sync bf16 hi/lo split ----------------
// 256 threads, 8 warps, occ 2. Fused per-channel stat accumulation in epilogue.
template<int D>
__global__ void __launch_bounds__(256,2)
k_convM(const float* __restrict__ in, float* __restrict__ out,
        const uint32_t* __restrict__ wBh, const uint32_t* __restrict__ wBl,
        const float* __restrict__ sSi, const float* __restrict__ sQi,
        const float* __restrict__ gm,  const float* __restrict__ bt,
        float* __restrict__ sSo, float* __restrict__ sQo,
        const float* __restrict__ resIn, float* __restrict__ resOut){
  constexpr int TW2  = 16+2*D;
  constexpr int PLHW = (D==1)?328:((D==2)?424:584);
  constexpr int TILE_W = 16*PLHW;
  extern __shared__ uint32_t smu[];
  uint32_t* tileH = smu;
  uint32_t* tileL = smu + TILE_W;
  uint32_t* Bh    = smu + 2*TILE_W;     // 2 x 1152
  uint32_t* Bl    = Bh + 2*1152;        // 2 x 1152
  float* aS = (float*)(Bl + 2*1152);    // 64
  float* cS = aS + 64;                  // 64
  float* red = cS + 64;                 // 512

  int tid = threadIdx.x;
  int lane = tid & 31, wid = tid >> 5;
  int wm = wid >> 1, wn = wid & 1;
  int g = lane >> 2, tig = lane & 3;
  int x0 = blockIdx.x*16, y0 = blockIdx.y*16;

  bool doAct = (gm != nullptr);
  bool hasRes = (resIn != nullptr);
  bool wAct = (resOut != nullptr);
  if(tid < 64){
    if(doAct){ float a,cc; aff_from_stats(sSi,sQi,gm,bt,tid,a,cc); aS[tid]=a; cS[tid]=cc; }
    else { aS[tid]=1.f; cS[tid]=0.f; }
  }

  float acc[4][4][4];
  #pragma unroll
  for(int j=0;j<4;j++)
    #pragma unroll
    for(int na=0;na<4;na++)
      #pragma unroll
      for(int q=0;q<4;q++) acc[j][na][q]=0.f;

  for(int half=0; half<2; half++){
    __syncthreads();
    for(int idx=tid; idx<16*TW2*TW2; idx+=256){
      int cp = idx/(TW2*TW2); int rr = idx - cp*(TW2*TW2);
      int r = rr/TW2, c2 = rr - r*TW2;
      int gy = y0 - D + r, gx = x0 - D + c2;
      float v0=0.f, v1=0.f;
      if(((unsigned)gy<384u) && ((unsigned)gx<384u)){
        int ci0 = half*32 + cp*2;
        int off0 = ci0*NHW + gy*LDIM + gx;
        float u0 = in[off0], u1 = in[off0+NHW];
        if(hasRes){
          float t0 = aS[ci0]*u0 + cS[ci0];
          float t1 = aS[ci0+1]*u1 + cS[ci0+1];
          v0 = fmaxf(t0, 0.01f*t0) + resIn[off0];
          v1 = fmaxf(t1, 0.01f*t1) + resIn[off0+NHW];
          if((unsigned)(gy-y0)<16u && (unsigned)(gx-x0)<16u){
            resOut[off0] = v0; resOut[off0+NHW] = v1;
          }
        } else if(doAct){
          float t0 = aS[ci0]*u0 + cS[ci0];     v0 = fmaxf(t0, 0.01f*t0);
          float t1 = aS[ci0+1]*u1 + cS[ci0+1]; v1 = fmaxf(t1, 0.01f*t1);
          if(wAct && (unsigned)(gy-y0)<16u && (unsigned)(gx-x0)<16u){
            resOut[off0] = v0; resOut[off0+NHW] = v1;
          }
        } else { v0=u0; v1=u1; }
      }
      uint32_t hp, lp;
      bf16split2(v0, v1, hp, lp);
      int off = cp*PLHW + r*TW2 + c2;
      tileH[off] = hp; tileL[off] = lp;
    }
    const uint4* bsrcH = (const uint4*)(wBh + (half*9)*1152);
    const uint4* bsrcL = (const uint4*)(wBl + (half*9)*1152);
    for(int i=tid;i<288;i+=256){ ((uint4*)Bh)[i]=bsrcH[i]; ((uint4*)Bl)[i]=bsrcL[i]; }
    __syncthreads();

    for(int tap=0; tap<9; tap++){
      int buf = tap & 1;
      if(tap < 8){
        const uint4* nh = bsrcH + (tap+1)*288;
        const uint4* nl = bsrcL + (tap+1)*288;
        uint4* dh = (uint4*)(Bh + (buf^1)*1152);
        uint4* dl = (uint4*)(Bl + (buf^1)*1152);
        for(int i=tid;i<288;i+=256){ dh[i]=nh[i]; dl[i]=nl[i]; }
      }
      int ky = tap/3, kx = tap - ky*3;
      #pragma unroll
      for(int kc=0;kc<2;kc++){
        uint32_t AH[4][4], AL[4][4];
        const uint32_t* tb = tileH + (kc*8+tig)*PLHW + (ky*D)*TW2 + kx*D + g;
        #pragma unroll
        for(int j=0;j<4;j++){
          const uint32_t* th = tb + (wm*4+j)*TW2;
          AH[j][0]=th[0]; AH[j][1]=th[8]; AH[j][2]=th[4*PLHW]; AH[j][3]=th[4*PLHW+8];
          const uint32_t* tl = th + TILE_W;
          AL[j][0]=tl[0]; AL[j][1]=tl[8]; AL[j][2]=tl[4*PLHW]; AL[j][3]=tl[4*PLHW+8];
        }
        const uint32_t* bbh = Bh + buf*1152 + (kc*8+tig)*72 + wn*32 + g;
        const uint32_t* bbl = Bl + buf*1152 + (kc*8+tig)*72 + wn*32 + g;
        #pragma unroll
        for(int na=0;na<4;na++){
          uint32_t bh0 = bbh[na*8], bh1 = bbh[na*8 + 4*72];
          uint32_t bl0 = bbl[na*8], bl1 = bbl[na*8 + 4*72];
          #pragma unroll
          for(int j=0;j<4;j++) MMA16816(acc[j][na], AH[j], bh0, bh1);
          #pragma unroll
          for(int j=0;j<4;j++) MMA16816(acc[j][na], AH[j], bl0, bl1);
          #pragma unroll
          for(int j=0;j<4;j++) MMA16816(acc[j][na], AL[j], bh0, bh1);
        }
      }
      __syncthreads();
    }
  }
  // epilogue: write output
  #pragma unroll
  for(int j=0;j<4;j++){
    int gy = y0 + wm*4 + j;
    #pragma unroll
    for(int na=0;na<4;na++){
      int co = wn*32 + na*8 + tig*2;
      float* op = out + co*NHW + gy*LDIM + x0;
      op[g]         = acc[j][na][0];
      op[NHW + g]   = acc[j][na][1];
      op[g+8]       = acc[j][na][2];
      op[NHW + g+8] = acc[j][na][3];
    }
  }
  // fused per-channel stats
  float sv[16];
  #pragma unroll
  for(int na=0;na<4;na++){
    #pragma unroll
    for(int par=0;par<2;par++){
      float s=0.f, q=0.f;
      #pragma unroll
      for(int j=0;j<4;j++){
        float v0=acc[j][na][par], v1=acc[j][na][par+2];
        s += v0+v1; q += v0*v0+v1*v1;
      }
      sv[(na*2+par)*2]   = s;
      sv[(na*2+par)*2+1] = q;
    }
  }
  #pragma unroll
  for(int off=4; off<32; off<<=1){
    #pragma unroll
    for(int i=0;i<16;i++) sv[i] += __shfl_xor_sync(0xffffffffu, sv[i], off);
  }
  if(lane<4){
    #pragma unroll
    for(int i=0;i<16;i++) red[wid*64 + lane*16 + i] = sv[i];
  }
  __syncthreads();
  if(tid<128){
    int sq = tid>>6, ch = tid&63;
    int wn_=ch>>5, na_=(ch>>3)&3, tg=(ch>>1)&3, par=ch&1;
    float tot=0.f;
    #pragma unroll
    for(int k=0;k<4;k++) tot += red[(2*k+wn_)*64 + tg*16 + (na_*2+par)*2 + sq];
    REDADD((sq? sQo : sSo)+ch, tot);
  }
}

// ---------------- host ----------------
static void launch_conv(int d, const float* in, float* out,
                        const uint32_t* wh, const uint32_t* wl,
                        const float* sSi, const float* sQi,
                        const float* gm, const float* bt,
                        float* sSo, float* sQo,
                        const float* resIn, float* resOut){
  dim3 g(24,24);
  if(d==1)      k_convM<1><<<g,256,62976>>>(in,out,wh,wl,sSi,sQi,gm,bt,sSo,sQo,resIn,resOut);
  else if(d==2) k_convM<2><<<g,256,75264>>>(in,out,wh,wl,sSi,sQi,gm,bt,sSo,sQo,resIn,resOut);
  else          k_convM<4><<<g,256,95744>>>(in,out,wh,wl,sSi,sQi,gm,bt,sSo,sQo,resIn,resOut);
}

extern "C" void kernel_launch(void* const* d_in, const int* in_sizes, int n_in,
                              void* d_out, int out_size){
  const float* x1 =(const float*)d_in[0];
  const float* x2 =(const float*)d_in[1];
  const float* W1 =(const float*)d_in[2];
  const float* g1 =(const float*)d_in[3];
  const float* b1 =(const float*)d_in[4];
  const float* W2 =(const float*)d_in[5];
  const float* g2 =(const float*)d_in[6];
  const float* b2 =(const float*)d_in[7];
  const float* W3 =(const float*)d_in[8];
  const float* g3 =(const float*)d_in[9];
  const float* b3 =(const float*)d_in[10];
  const float* rw =(const float*)d_in[11];
  const float* rg =(const float*)d_in[13];
  const float* rbe=(const float*)d_in[14];
  float* outp=(float*)d_out;

  float *bufT,*bufU,*bufX,*bufV,*sS,*sQ;
  uint32_t *wBh,*wBl;
  cudaGetSymbolAddress((void**)&bufT, g_bufT);
  cudaGetSymbolAddress((void**)&bufU, g_bufU);
  cudaGetSymbolAddress((void**)&bufX, g_bufX);
  cudaGetSymbolAddress((void**)&bufV, g_bufV);
  cudaGetSymbolAddress((void**)&wBh,  g_wBh);
  cudaGetSymbolAddress((void**)&wBl,  g_wBl);
  cudaGetSymbolAddress((void**)&sS,   g_sS);
  cudaGetSymbolAddress((void**)&sQ,   g_sQ);

  cudaFuncSetAttribute(k_convM<1>, cudaFuncAttributeMaxDynamicSharedMemorySize, 62976);
  cudaFuncSetAttribute(k_convM<2>, cudaFuncAttributeMaxDynamicSharedMemorySize, 75264);
  cudaFuncSetAttribute(k_convM<4>, cudaFuncAttributeMaxDynamicSharedMemorySize, 95744);
  cudaFuncSetAttribute(k_pair2,    cudaFuncAttributeMaxDynamicSharedMemorySize, 61440);
  cudaFuncSetAttribute(k_pair,     cudaFuncAttributeMaxDynamicSharedMemorySize, 67584);

  k_zero<<<48,512>>>();
  k_front<<<2348,256>>>(x1, x2, rw);
  k_fold<<<(CH*ND1+CH*ND2+255)/256,256>>>(W1, W2);
  k_rowcol<<<dim3(64,8),384>>>(x1);
  k_rcstats<<<64,128>>>(g1,b1);
  k_pair2<<<576,256,61440>>>(x2);
  k_cstats<<<dim3(64,8),256>>>(bufU, sS+0*64, sQ+0*64);       // set 0: pair2 out
  k_pair<<<2304,256,67584>>>(W3, g2, b2);                      // uses set 0
  k_cstats<<<dim3(64,8),256>>>(bufX, sS+1*64, sQ+1*64);       // set 1: pair out (raw)

  const int dil[5]={1,2,4,2,1};
  float* resBuf[2] = {bufV, bufX};
  int cur = 0;   // bufV will hold the activated pair output (residual) after conv1-l0
  for(int l=0;l<5;l++){
    int d=dil[l];
    const uint32_t* wh0 = wBh + (l*2  )*20736;
    const uint32_t* wl0 = wBl + (l*2  )*20736;
    const uint32_t* wh1 = wBh + (l*2+1)*20736;
    const uint32_t* wl1 = wBl + (l*2+1)*20736;
    float* s0S = sS + (2+2*l)*64;  float* s0Q = sQ + (2+2*l)*64;
    float* s1S = sS + (3+2*l)*64;  float* s1Q = sQ + (3+2*l)*64;
    if(l==0){
      launch_conv(d, bufX, bufT, wh0, wl0,
                  sS+1*64, sQ+1*64, g3, b3, s0S, s0Q, nullptr, bufV);
    } else {
      float* sPS = sS + (1+2*l)*64;  float* sPQ = sQ + (1+2*l)*64;
      launch_conv(d, bufU, bufT, wh0, wl0,
                  sPS, sPQ, rg+(2*l-1)*CH, rbe+(2*l-1)*CH, s0S, s0Q,
                  resBuf[cur], resBuf[cur^1]);
      cur ^= 1;
    }
    launch_conv(d, bufT, bufU, wh1, wl1,
                s0S, s0Q, rg+(2*l)*CH, rbe+(2*l)*CH, s1S, s1Q, nullptr,nullptr);
  }
  k_apply_res<<<dim3(144,64),256>>>(bufU, resBuf[cur], outp,
                                    sS+11*64, sQ+11*64, rg+9*CH, rbe+9*CH);
}

// round 16
// speedup vs baseline: 1.0774x; 1.0120x over previous
#include <cuda_runtime.h>
#include <cstdint>

constexpr int LDIM = 384;
constexpr int NHW  = 147456;   // 384*384
constexpr int CH   = 64;
constexpr int ND1  = 788;
constexpr int ND2  = 210;
#define EPSV 1e-5f

// ---------------- device scratch (static, no allocations) ----------------
__device__ float g_bufT[CH*NHW];
__device__ float g_bufU[CH*NHW];
__device__ float g_bufX[CH*NHW];
__device__ float g_bufV[CH*NHW];   // residual ping-pong partner of bufX
__device__ float g_rs1[ND1];
__device__ float g_W1af[CH*ND1];
__device__ float g_W1bf[CH*ND1];
__device__ float g_W2f[CH*ND2];
__device__ float g_row[CH*LDIM];
__device__ float g_col[CH*LDIM];
__device__ float g_a1[CH], g_c1[CH];
__device__ float g_accS[ND2], g_accQ[ND2];
// 12 per-channel stat sets (sum / sumsq), each written once per run
__device__ float g_sS[12*64];
__device__ float g_sQ[12*64];
// conv weights as B-fragment words: [lk][half][tap][cipair 16][72 (64 used)]
__device__ uint32_t g_wBh[10*2*9*16*72];
__device__ uint32_t g_wBl[10*2*9*16*72];

__device__ __forceinline__ float lrelu(float v){ return fmaxf(v, 0.01f*v); }

__device__ __forceinline__ float wsum(float v){
  #pragma unroll
  for(int o=16;o>0;o>>=1) v += __shfl_down_sync(0xffffffffu, v, o);
  return v;
}

__device__ __forceinline__ void bf16split2(float v0, float v1, uint32_t& hp, uint32_t& lp){
  asm("cvt.rn.bf16x2.f32 %0, %1, %2;" : "=r"(hp) : "f"(v1), "f"(v0));
  float h0 = __uint_as_float(hp<<16);
  float h1 = __uint_as_float(hp & 0xffff0000u);
  float l0 = v0 - h0, l1 = v1 - h1;
  asm("cvt.rn.bf16x2.f32 %0, %1, %2;" : "=r"(lp) : "f"(l1), "f"(l0));
}

#define MMA16816(d, a, b0, b1) \
  asm volatile("mma.sync.aligned.m16n8k16.row.col.f32.bf16.bf16.f32 " \
    "{%0,%1,%2,%3}, {%4,%5,%6,%7}, {%8,%9}, {%0,%1,%2,%3};" \
    : "+f"((d)[0]),"+f"((d)[1]),"+f"((d)[2]),"+f"((d)[3]) \
    : "r"((a)[0]),"r"((a)[1]),"r"((a)[2]),"r"((a)[3]), "r"(b0),"r"(b1))

#define REDADD(p, v) asm volatile("red.global.add.f32 [%0], %1;" :: "l"(p), "f"(v) : "memory")

__device__ __forceinline__ void aff_from_stats(const float* sS, const float* sQ,
                                               const float* gm, const float* bt,
                                               int c, float& a, float& cc){
  float mu = sS[c]*(1.f/(float)NHW);
  float var = sQ[c]*(1.f/(float)NHW) - mu*mu;
  a = gm[c]*rsqrtf(var+EPSV);
  cc = bt[c]-mu*a;
}

// ---------------- small kernels ----------------
__global__ void k_zero(){
  int t = blockIdx.x*512 + threadIdx.x;
  if(t < 768){ g_sS[t]=0.f; g_sQ[t]=0.f; }
  if(t < ND2){ g_accS[t]=0.f; g_accQ[t]=0.f; }
  if(t < CH*LDIM){ g_row[t]=0.f; g_col[t]=0.f; }
}

// merged front kernel: blocks [0,788) stats1d, [788,1628) stats2, [1628,2348) prepB
__global__ void k_front(const float* __restrict__ x1, const float* __restrict__ x2,
                        const float* __restrict__ rw){
  int b = blockIdx.x;
  int tid = threadIdx.x;
  if(b < 788){
    const float* p = x1 + b*LDIM;
    float s=0.f,q=0.f;
    for(int i=tid;i<LDIM;i+=256){ float v=p[i]; s+=v; q+=v*v; }
    __shared__ float ss[8], sq[8];
    s = wsum(s); q = wsum(q);
    int w = tid>>5, ln = tid&31;
    if(ln==0){ ss[w]=s; sq[w]=q; }
    __syncthreads();
    if(tid==0){
      float S=0.f,Q=0.f;
      #pragma unroll
      for(int i=0;i<8;i++){S+=ss[i];Q+=sq[i];}
      float mu=S/(float)LDIM; float var=Q/(float)LDIM-mu*mu;
      g_rs1[b]=rsqrtf(var+EPSV);
    }
  } else if(b < 1628){
    int i = b-788;
    int d = i>>2, seg = i&3;
    const float4* p = (const float4*)(x2 + d*NHW + seg*36864);
    float s=0.f,q=0.f;
    for(int i2=tid;i2<9216;i2+=256){
      float4 v=p[i2];
      s += v.x+v.y+v.z+v.w;
      q += v.x*v.x+v.y*v.y+v.z*v.z+v.w*v.w;
    }
    __shared__ float ss2[8], sq2[8];
    s=wsum(s); q=wsum(q);
    int w=tid>>5, ln=tid&31;
    if(ln==0){ ss2[w]=s; sq2[w]=q; }
    __syncthreads();
    if(tid==0){
      float S=0.f,Q=0.f;
      #pragma unroll
      for(int i2=0;i2<8;i2++){S+=ss2[i2];Q+=sq2[i2];}
      atomicAdd(&g_accS[d],S); atomicAdd(&g_accQ[d],Q);
    }
  } else {
    int idx = (b-1628)*256 + tid;
    if(idx >= 10*2*9*16*64) return;
    int n   = idx & 63;
    int cp  = (idx>>6) & 15;
    int tap = (idx>>10) % 9;
    int rest= (idx>>10) / 9;
    int half= rest & 1;
    int lk  = rest >> 1;
    int ci0 = half*32 + cp*2;
    float w0 = rw[((lk*CH + n)*CH + ci0  )*9 + tap];
    float w1 = rw[((lk*CH + n)*CH + ci0+1)*9 + tap];
    uint32_t hp, lp;
    bf16split2(w0, w1, hp, lp);
    int o = ((rest*9 + tap)*16 + cp)*72 + n;
    g_wBh[o] = hp; g_wBl[o] = lp;
  }
}

// merged weight fold (rs2 computed inline from accumulated stats)
__global__ void k_fold(const float* __restrict__ W1, const float* __restrict__ W2){
  int idx = blockIdx.x*256+threadIdx.x;
  if(idx < CH*ND1){
    int c = idx/ND1, d = idx%ND1;
    float rs = g_rs1[d];
    g_W1af[idx] = W1[c*2*ND1 + d]*rs;
    g_W1bf[idx] = W1[c*2*ND1 + ND1 + d]*rs;
  } else {
    int i2 = idx - CH*ND1;
    if(i2 < CH*ND2){
      int d = i2%ND2;
      float mu = g_accS[d]*(1.f/(float)NHW);
      float var = g_accQ[d]*(1.f/(float)NHW) - mu*mu;
      g_W2f[i2] = W2[i2]*rsqrtf(var+EPSV);
    }
  }
}

// rowcol: grid (64 c, 16 segs), 384 threads; 4-way unrolled accumulators; atomic combine
__global__ void k_rowcol(const float* __restrict__ x1){
  int c = blockIdx.x, seg = blockIdx.y, i = threadIdx.x;
  const float* wa = g_W1af + c*ND1;
  const float* wb = g_W1bf + c*ND1;
  int d0 = seg*50;
  int d1 = d0+50; if(d1 > ND1) d1 = ND1;
  if(d0 >= ND1) return;
  float r0=0.f,r1=0.f,r2=0.f,r3=0.f,c0=0.f,c1=0.f,c2=0.f,c3=0.f;
  int d=d0;
  for(; d+3<d1; d+=4){
    float va = x1[d*LDIM + i];
    float vb = x1[(d+1)*LDIM + i];
    float vc = x1[(d+2)*LDIM + i];
    float vd = x1[(d+3)*LDIM + i];
    r0 += wa[d]*va;   c0 += wb[d]*va;
    r1 += wa[d+1]*vb; c1 += wb[d+1]*vb;
    r2 += wa[d+2]*vc; c2 += wb[d+2]*vc;
    r3 += wa[d+3]*vd; c3 += wb[d+3]*vd;
  }
  for(; d<d1; d++){ float v=x1[d*LDIM+i]; r0+=wa[d]*v; c0+=wb[d]*v; }
  atomicAdd(&g_row[c*LDIM+i], (r0+r1)+(r2+r3));
  atomicAdd(&g_col[c*LDIM+i], (c0+c1)+(c2+c3));
}

// rc stats -> a1/c1
__global__ void k_rcstats(const float* __restrict__ g1, const float* __restrict__ b1){
  int c = blockIdx.x;
  float sr=0.f,qr=0.f,sc=0.f,qc=0.f;
  for(int i=threadIdx.x;i<LDIM;i+=128){
    float r=g_row[c*LDIM+i], cl=g_col[c*LDIM+i];
    sr+=r; qr+=r*r; sc+=cl; qc+=cl*cl;
  }
  __shared__ float sm4[4][4];
  sr=wsum(sr); qr=wsum(qr); sc=wsum(sc); qc=wsum(qc);
  int w=threadIdx.x>>5, ln=threadIdx.x&31;
  if(ln==0){ sm4[w][0]=sr; sm4[w][1]=qr; sm4[w][2]=sc; sm4[w][3]=qc; }
  __syncthreads();
  if(threadIdx.x==0){
    float Sr=0.f,Qr=0.f,Sc=0.f,Qc=0.f;
    #pragma unroll
    for(int i=0;i<4;i++){Sr+=sm4[i][0];Qr+=sm4[i][1];Sc+=sm4[i][2];Qc+=sm4[i][3];}
    float mr=Sr/(float)LDIM, mc=Sc/(float)LDIM;
    float vr=Qr/(float)LDIM-mr*mr, vc=Qc/(float)LDIM-mc*mc;
    float rs=rsqrtf(vr+vc+EPSV);
    float a=g1[c]*rs;
    g_a1[c]=a; g_c1[c]=b1[c]-(mr+mc)*a;
  }
}

// pair2 GEMM with packed f32x2
__global__ void k_pair2(const float* __restrict__ x2){
  extern __shared__ float sm[];
  float* W2T = sm;            // [d][c] 210*64
  float* xs  = sm + 13440;    // 6*256
  int tid=threadIdx.x;
  for(int i=tid;i<13440;i+=256){ int d=i>>6, c=i&63; W2T[i]=g_W2f[c*ND2+d]; }
  int cg = tid>>7, pxl = tid&127;
  int pix0 = blockIdx.x*256;
  unsigned long long a0[16], a1[16];
  #pragma unroll
  for(int p=0;p<16;p++){ a0[p]=0ULL; a1[p]=0ULL; }
  __syncthreads();
  for(int d0=0; d0<ND2; d0+=6){
    for(int i=tid;i<384;i+=256)
      ((float4*)xs)[i] = ((const float4*)(x2 + (d0 + (i>>6))*NHW + pix0))[i&63];
    __syncthreads();
    #pragma unroll
    for(int dd=0;dd<6;dd++){
      float2 v = *(const float2*)(xs + dd*256 + pxl*2);
      unsigned long long dv0, dv1;
      asm("mov.b64 %0, {%1,%1};" : "=l"(dv0) : "f"(v.x));
      asm("mov.b64 %0, {%1,%1};" : "=l"(dv1) : "f"(v.y));
      const unsigned long long* wp = (const unsigned long long*)(W2T + (d0+dd)*64 + cg*32);
      #pragma unroll
      for(int p=0;p<16;p++){
        unsigned long long w2 = wp[p];
        asm("fma.rn.f32x2 %0, %1, %2, %0;" : "+l"(a0[p]) : "l"(w2), "l"(dv0));
        asm("fma.rn.f32x2 %0, %1, %2, %0;" : "+l"(a1[p]) : "l"(w2), "l"(dv1));
      }
    }
    __syncthreads();
  }
  int P = pix0 + pxl*2;
  #pragma unroll
  for(int p=0;p<16;p++){
    float l0,h0,l1,h1;
    asm("mov.b64 {%0,%1}, %2;" : "=f"(l0), "=f"(h0) : "l"(a0[p]));
    asm("mov.b64 {%0,%1}, %2;" : "=f"(l1), "=f"(h1) : "l"(a1[p]));
    int c = cg*32 + 2*p;
    g_bufU[c*NHW + P]       = l0;
    g_bufU[c*NHW + P + 1]   = l1;
    g_bufU[(c+1)*NHW + P]   = h0;
    g_bufU[(c+1)*NHW + P+1] = h1;
  }
}

// per-channel sum/sumsq accumulate into a stat set (float4, 16 segs)
__global__ void k_cstats(const float* __restrict__ buf, float* __restrict__ sS, float* __restrict__ sQ){
  int c=blockIdx.x, seg=blockIdx.y;
  const float4* p = (const float4*)(buf + c*NHW + seg*9216);
  float s=0.f,q=0.f;
  for(int i=threadIdx.x;i<2304;i+=256){
    float4 v=p[i];
    s += v.x+v.y+v.z+v.w;
    q += v.x*v.x+v.y*v.y+v.z*v.z+v.w*v.w;
  }
  __shared__ float ss[8], sq[8];
  s=wsum(s); q=wsum(q);
  int w=threadIdx.x>>5, ln=threadIdx.x&31;
  if(ln==0){ ss[w]=s; sq[w]=q; }
  __syncthreads();
  if(threadIdx.x==0){
    float S=0.f,Q=0.f;
    #pragma unroll
    for(int i=0;i<8;i++){S+=ss[i];Q+=sq[i];}
    atomicAdd(&sS[c],S); atomicAdd(&sQ[c],Q);
  }
}

// pair stage, f32x2 (a2/c2 computed inline from stat set 0)
__global__ void k_pair(const float* __restrict__ W3,
                       const float* __restrict__ g2, const float* __restrict__ b2){
  extern __shared__ float sm[];
  float* WaT = sm;             // [d][c] stride 66
  float* WbT = sm + 64*66;
  float* p1s = sm + 2*64*66;
  float* p2s = p1s + 4096;
  float* aS2 = p2s + 4096;     // 64
  float* cS2 = aS2 + 64;       // 64
  int tid=threadIdx.x;
  for(int i=tid;i<4096;i+=256){
    int d=i&63, c=i>>6;
    WaT[d*66+c]=W3[c*128+d];
    WbT[d*66+c]=W3[c*128+64+d];
  }
  if(tid<64){ float a,cc; aff_from_stats(g_sS, g_sQ, g2, b2, tid, a, cc); aS2[tid]=a; cS2[tid]=cc; }
  __syncthreads();
  int P0 = blockIdx.x*64;
  int i0 = P0/LDIM, j0 = P0 - i0*LDIM;
  for(int idx=tid;idx<4096;idx+=256){
    int c=idx>>6, px=idx&63;
    float v1 = g_row[c*LDIM+i0] + g_col[c*LDIM+j0+px];
    p1s[idx] = lrelu(g_a1[c]*v1 + g_c1[c]);
    float u = g_bufU[c*NHW + P0 + px];
    p2s[idx] = lrelu(aS2[c]*u + cS2[c]);
  }
  __syncthreads();
  int pi=tid&31, cg=tid>>5;
  unsigned long long acc[8];
  #pragma unroll
  for(int p=0;p<8;p++) acc[p]=0ULL;
  for(int dd=0;dd<64;dd++){
    float2 v1 = *(const float2*)(p1s + dd*64 + pi*2);
    float2 v2 = *(const float2*)(p2s + dd*64 + pi*2);
    unsigned long long s10,s11,s20,s21;
    asm("mov.b64 %0, {%1,%1};" : "=l"(s10) : "f"(v1.x));
    asm("mov.b64 %0, {%1,%1};" : "=l"(s11) : "f"(v1.y));
    asm("mov.b64 %0, {%1,%1};" : "=l"(s20) : "f"(v2.x));
    asm("mov.b64 %0, {%1,%1};" : "=l"(s21) : "f"(v2.y));
    const unsigned long long* wa = (const unsigned long long*)(WaT + dd*66 + cg*8);
    const unsigned long long* wb = (const unsigned long long*)(WbT + dd*66 + cg*8);
    #pragma unroll
    for(int p=0;p<4;p++){
      unsigned long long wA=wa[p], wB=wb[p];
      asm("fma.rn.f32x2 %0, %1, %2, %0;" : "+l"(acc[p*2  ]) : "l"(wA), "l"(s10));
      asm("fma.rn.f32x2 %0, %1, %2, %0;" : "+l"(acc[p*2  ]) : "l"(wB), "l"(s20));
      asm("fma.rn.f32x2 %0, %1, %2, %0;" : "+l"(acc[p*2+1]) : "l"(wA), "l"(s11));
      asm("fma.rn.f32x2 %0, %1, %2, %0;" : "+l"(acc[p*2+1]) : "l"(wB), "l"(s21));
    }
  }
  #pragma unroll
  for(int p=0;p<4;p++){
    #pragma unroll
    for(int q=0;q<2;q++){
      float lo,hi;
      asm("mov.b64 {%0,%1}, %2;" : "=f"(lo), "=f"(hi) : "l"(acc[p*2+q]));
      int c = cg*8 + 2*p;
      int P = P0 + pi*2 + q;
      g_bufX[c*NHW + P]     = lo;
      g_bufX[(c+1)*NHW + P] = hi;
    }
  }
}

__global__ void k_apply_res(const float* __restrict__ u, const float* __restrict__ res,
                            float* __restrict__ o,
                            const float* __restrict__ sS, const float* __restrict__ sQ,
                            const float* __restrict__ gm, const float* __restrict__ bt){
  int c=blockIdx.y;
  float a,cc; aff_from_stats(sS,sQ,gm,bt,c,a,cc);
  int idx = blockIdx.x*128 + threadIdx.x;
  float4 uv = ((const float4*)(u + c*NHW))[idx];
  float4 rv = ((const float4*)(res + c*NHW))[idx];
  float4 ov;
  ov.x = lrelu(a*uv.x+cc)+rv.x; ov.y = lrelu(a*uv.y+cc)+rv.y;
  ov.z = lrelu(a*uv.z+cc)+rv.z; ov.w = lrelu(a*uv.w+cc)+rv.w;
  ((float4*)(o + c*NHW))[idx] = ov;
}

// ---------------- conv 3x3 dilated 64->64 via mma.sync bf16 hi/lo split ----------------
// 256 threads, 8 warps, occ 2. Fused per-channel stat accumulation in epilogue.
template<int D>
__global__ void __launch_bounds__(256,2)
k_convM(const float* __restrict__ in, float* __restrict__ out,
        const uint32_t* __restrict__ wBh, const uint32_t* __restrict__ wBl,
        const float* __restrict__ sSi, const float* __restrict__ sQi,
        const float* __restrict__ gm,  const float* __restrict__ bt,
        float* __restrict__ sSo, float* __restrict__ sQo,
        const float* __restrict__ resIn, float* __restrict__ resOut){
  constexpr int TW2  = 16+2*D;
  constexpr int PLHW = (D==1)?328:((D==2)?424:584);
  constexpr int TILE_W = 16*PLHW;
  extern __shared__ uint32_t smu[];
  uint32_t* tileH = smu;
  uint32_t* tileL = smu + TILE_W;
  uint32_t* Bh    = smu + 2*TILE_W;     // 2 x 1152
  uint32_t* Bl    = Bh + 2*1152;        // 2 x 1152
  float* aS = (float*)(Bl + 2*1152);    // 64
  float* cS = aS + 64;                  // 64
  float* red = cS + 64;                 // 512

  int tid = threadIdx.x;
  int lane = tid & 31, wid = tid >> 5;
  int wm = wid >> 1, wn = wid & 1;
  int g = lane >> 2, tig = lane & 3;
  int x0 = blockIdx.x*16, y0 = blockIdx.y*16;

  bool doAct = (gm != nullptr);
  bool hasRes = (resIn != nullptr);
  bool wAct = (resOut != nullptr);
  if(tid < 64){
    if(doAct){ float a,cc; aff_from_stats(sSi,sQi,gm,bt,tid,a,cc); aS[tid]=a; cS[tid]=cc; }
    else { aS[tid]=1.f; cS[tid]=0.f; }
  }

  float acc[4][4][4];
  #pragma unroll
  for(int j=0;j<4;j++)
    #pragma unroll
    for(int na=0;na<4;na++)
      #pragma unroll
      for(int q=0;q<4;q++) acc[j][na][q]=0.f;

  for(int half=0; half<2; half++){
    __syncthreads();
    for(int idx=tid; idx<16*TW2*TW2; idx+=256){
      int cp = idx/(TW2*TW2); int rr = idx - cp*(TW2*TW2);
      int r = rr/TW2, c2 = rr - r*TW2;
      int gy = y0 - D + r, gx = x0 - D + c2;
      float v0=0.f, v1=0.f;
      if(((unsigned)gy<384u) && ((unsigned)gx<384u)){
        int ci0 = half*32 + cp*2;
        int off0 = ci0*NHW + gy*LDIM + gx;
        float u0 = in[off0], u1 = in[off0+NHW];
        if(hasRes){
          float t0 = aS[ci0]*u0 + cS[ci0];
          float t1 = aS[ci0+1]*u1 + cS[ci0+1];
          v0 = fmaxf(t0, 0.01f*t0) + resIn[off0];
          v1 = fmaxf(t1, 0.01f*t1) + resIn[off0+NHW];
          if((unsigned)(gy-y0)<16u && (unsigned)(gx-x0)<16u){
            resOut[off0] = v0; resOut[off0+NHW] = v1;
          }
        } else if(doAct){
          float t0 = aS[ci0]*u0 + cS[ci0];     v0 = fmaxf(t0, 0.01f*t0);
          float t1 = aS[ci0+1]*u1 + cS[ci0+1]; v1 = fmaxf(t1, 0.01f*t1);
          if(wAct && (unsigned)(gy-y0)<16u && (unsigned)(gx-x0)<16u){
            resOut[off0] = v0; resOut[off0+NHW] = v1;
          }
        } else { v0=u0; v1=u1; }
      }
      uint32_t hp, lp;
      bf16split2(v0, v1, hp, lp);
      int off = cp*PLHW + r*TW2 + c2;
      tileH[off] = hp; tileL[off] = lp;
    }
    const uint4* bsrcH = (const uint4*)(wBh + (half*9)*1152);
    const uint4* bsrcL = (const uint4*)(wBl + (half*9)*1152);
    for(int i=tid;i<288;i+=256){ ((uint4*)Bh)[i]=bsrcH[i]; ((uint4*)Bl)[i]=bsrcL[i]; }
    __syncthreads();

    for(int tap=0; tap<9; tap++){
      int buf = tap & 1;
      if(tap < 8){
        const uint4* nh = bsrcH + (tap+1)*288;
        const uint4* nl = bsrcL + (tap+1)*288;
        uint4* dh = (uint4*)(Bh + (buf^1)*1152);
        uint4* dl = (uint4*)(Bl + (buf^1)*1152);
        for(int i=tid;i<288;i+=256){ dh[i]=nh[i]; dl[i]=nl[i]; }
      }
      int ky = tap/3, kx = tap - ky*3;
      #pragma unroll
      for(int kc=0;kc<2;kc++){
        uint32_t AH[4][4], AL[4][4];
        const uint32_t* tb = tileH + (kc*8+tig)*PLHW + (ky*D)*TW2 + kx*D + g;
        #pragma unroll
        for(int j=0;j<4;j++){
          const uint32_t* th = tb + (wm*4+j)*TW2;
          AH[j][0]=th[0]; AH[j][1]=th[8]; AH[j][2]=th[4*PLHW]; AH[j][3]=th[4*PLHW+8];
          const uint32_t* tl = th + TILE_W;
          AL[j][0]=tl[0]; AL[j][1]=tl[8]; AL[j][2]=tl[4*PLHW]; AL[j][3]=tl[4*PLHW+8];
        }
        const uint32_t* bbh = Bh + buf*1152 + (kc*8+tig)*72 + wn*32 + g;
        const uint32_t* bbl = Bl + buf*1152 + (kc*8+tig)*72 + wn*32 + g;
        #pragma unroll
        for(int na=0;na<4;na++){
          uint32_t bh0 = bbh[na*8], bh1 = bbh[na*8 + 4*72];
          uint32_t bl0 = bbl[na*8], bl1 = bbl[na*8 + 4*72];
          #pragma unroll
          for(int j=0;j<4;j++) MMA16816(acc[j][na], AH[j], bh0, bh1);
          #pragma unroll
          for(int j=0;j<4;j++) MMA16816(acc[j][na], AH[j], bl0, bl1);
          #pragma unroll
          for(int j=0;j<4;j++) MMA16816(acc[j][na], AL[j], bh0, bh1);
        }
      }
      __syncthreads();
    }
  }
  // epilogue: write output
  #pragma unroll
  for(int j=0;j<4;j++){
    int gy = y0 + wm*4 + j;
    #pragma unroll
    for(int na=0;na<4;na++){
      int co = wn*32 + na*8 + tig*2;
      float* op = out + co*NHW + gy*LDIM + x0;
      op[g]         = acc[j][na][0];
      op[NHW + g]   = acc[j][na][1];
      op[g+8]       = acc[j][na][2];
      op[NHW + g+8] = acc[j][na][3];
    }
  }
  // fused per-channel stats
  float sv[16];
  #pragma unroll
  for(int na=0;na<4;na++){
    #pragma unroll
    for(int par=0;par<2;par++){
      float s=0.f, q=0.f;
      #pragma unroll
      for(int j=0;j<4;j++){
        float v0=acc[j][na][par], v1=acc[j][na][par+2];
        s += v0+v1; q += v0*v0+v1*v1;
      }
      sv[(na*2+par)*2]   = s;
      sv[(na*2+par)*2+1] = q;
    }
  }
  #pragma unroll
  for(int off=4; off<32; off<<=1){
    #pragma unroll
    for(int i=0;i<16;i++) sv[i] += __shfl_xor_sync(0xffffffffu, sv[i], off);
  }
  if(lane<4){
    #pragma unroll
    for(int i=0;i<16;i++) red[wid*64 + lane*16 + i] = sv[i];
  }
  __syncthreads();
  if(tid<128){
    int sq = tid>>6, ch = tid&63;
    int wn_=ch>>5, na_=(ch>>3)&3, tg=(ch>>1)&3, par=ch&1;
    float tot=0.f;
    #pragma unroll
    for(int k=0;k<4;k++) tot += red[(2*k+wn_)*64 + tg*16 + (na_*2+par)*2 + sq];
    REDADD((sq? sQo : sSo)+ch, tot);
  }
}

// ---------------- host ----------------
static void launch_conv(int d, const float* in, float* out,
                        const uint32_t* wh, const uint32_t* wl,
                        const float* sSi, const float* sQi,
                        const float* gm, const float* bt,
                        float* sSo, float* sQo,
                        const float* resIn, float* resOut){
  dim3 g(24,24);
  if(d==1)      k_convM<1><<<g,256,62976>>>(in,out,wh,wl,sSi,sQi,gm,bt,sSo,sQo,resIn,resOut);
  else if(d==2) k_convM<2><<<g,256,75264>>>(in,out,wh,wl,sSi,sQi,gm,bt,sSo,sQo,resIn,resOut);
  else          k_convM<4><<<g,256,95744>>>(in,out,wh,wl,sSi,sQi,gm,bt,sSo,sQo,resIn,resOut);
}

extern "C" void kernel_launch(void* const* d_in, const int* in_sizes, int n_in,
                              void* d_out, int out_size){
  const float* x1 =(const float*)d_in[0];
  const float* x2 =(const float*)d_in[1];
  const float* W1 =(const float*)d_in[2];
  const float* g1 =(const float*)d_in[3];
  const float* b1 =(const float*)d_in[4];
  const float* W2 =(const float*)d_in[5];
  const float* g2 =(const float*)d_in[6];
  const float* b2 =(const float*)d_in[7];
  const float* W3 =(const float*)d_in[8];
  const float* g3 =(const float*)d_in[9];
  const float* b3 =(const float*)d_in[10];
  const float* rw =(const float*)d_in[11];
  const float* rg =(const float*)d_in[13];
  const float* rbe=(const float*)d_in[14];
  float* outp=(float*)d_out;

  float *bufT,*bufU,*bufX,*bufV,*sS,*sQ;
  uint32_t *wBh,*wBl;
  cudaGetSymbolAddress((void**)&bufT, g_bufT);
  cudaGetSymbolAddress((void**)&bufU, g_bufU);
  cudaGetSymbolAddress((void**)&bufX, g_bufX);
  cudaGetSymbolAddress((void**)&bufV, g_bufV);
  cudaGetSymbolAddress((void**)&wBh,  g_wBh);
  cudaGetSymbolAddress((void**)&wBl,  g_wBl);
  cudaGetSymbolAddress((void**)&sS,   g_sS);
  cudaGetSymbolAddress((void**)&sQ,   g_sQ);

  cudaFuncSetAttribute(k_convM<1>, cudaFuncAttributeMaxDynamicSharedMemorySize, 62976);
  cudaFuncSetAttribute(k_convM<2>, cudaFuncAttributeMaxDynamicSharedMemorySize, 75264);
  cudaFuncSetAttribute(k_convM<4>, cudaFuncAttributeMaxDynamicSharedMemorySize, 95744);
  cudaFuncSetAttribute(k_pair2,    cudaFuncAttributeMaxDynamicSharedMemorySize, 61440);
  cudaFuncSetAttribute(k_pair,     cudaFuncAttributeMaxDynamicSharedMemorySize, 67584);

  k_zero<<<48,512>>>();
  k_front<<<2348,256>>>(x1, x2, rw);
  k_fold<<<(CH*ND1+CH*ND2+255)/256,256>>>(W1, W2);
  k_rowcol<<<dim3(64,16),384>>>(x1);
  k_rcstats<<<64,128>>>(g1,b1);
  k_pair2<<<576,256,61440>>>(x2);
  k_cstats<<<dim3(64,16),256>>>(bufU, sS+0*64, sQ+0*64);      // set 0: pair2 out
  k_pair<<<2304,256,67584>>>(W3, g2, b2);                      // uses set 0
  k_cstats<<<dim3(64,16),256>>>(bufX, sS+1*64, sQ+1*64);      // set 1: pair out (raw)

  const int dil[5]={1,2,4,2,1};
  float* resBuf[2] = {bufV, bufX};
  int cur = 0;   // bufV will hold the activated pair output (residual) after conv1-l0
  for(int l=0;l<5;l++){
    int d=dil[l];
    const uint32_t* wh0 = wBh + (l*2  )*20736;
    const uint32_t* wl0 = wBl + (l*2  )*20736;
    const uint32_t* wh1 = wBh + (l*2+1)*20736;
    const uint32_t* wl1 = wBl + (l*2+1)*20736;
    float* s0S = sS + (2+2*l)*64;  float* s0Q = sQ + (2+2*l)*64;
    float* s1S = sS + (3+2*l)*64;  float* s1Q = sQ + (3+2*l)*64;
    if(l==0){
      launch_conv(d, bufX, bufT, wh0, wl0,
                  sS+1*64, sQ+1*64, g3, b3, s0S, s0Q, nullptr, bufV);
    } else {
      float* sPS = sS + (1+2*l)*64;  float* sPQ = sQ + (1+2*l)*64;
      launch_conv(d, bufU, bufT, wh0, wl0,
                  sPS, sPQ, rg+(2*l-1)*CH, rbe+(2*l-1)*CH, s0S, s0Q,
                  resBuf[cur], resBuf[cur^1]);
      cur ^= 1;
    }
    launch_conv(d, bufT, bufU, wh1, wl1,
                s0S, s0Q, rg+(2*l)*CH, rbe+(2*l)*CH, s1S, s1Q, nullptr,nullptr);
  }
  k_apply_res<<<dim3(288,64),128>>>(bufU, resBuf[cur], outp,
                                    sS+11*64, sQ+11*64, rg+9*CH, rbe+9*CH);
}

// round 17
// speedup vs baseline: 1.0818x; 1.0041x over previous
#include <cuda_runtime.h>
#include <cstdint>

constexpr int LDIM = 384;
constexpr int NHW  = 147456;   // 384*384
constexpr int CH   = 64;
constexpr int ND1  = 788;
constexpr int ND2  = 210;
#define EPSV 1e-5f

// ---------------- device scratch (static, no allocations) ----------------
__device__ float g_bufT[CH*NHW];
__device__ float g_bufU[CH*NHW];
__device__ float g_bufX[CH*NHW];
__device__ float g_bufV[CH*NHW];   // residual ping-pong partner of bufX
__device__ float g_rs1[ND1];
__device__ float g_W1af[CH*ND1];
__device__ float g_W1bf[CH*ND1];
__device__ float g_W2f[CH*ND2];
__device__ float g_row[CH*LDIM];
__device__ float g_col[CH*LDIM];
__device__ float g_a1[CH], g_c1[CH];
__device__ float g_accS[ND2], g_accQ[ND2];
// 12 per-channel stat sets (sum / sumsq), each written once per run
__device__ float g_sS[12*64];
__device__ float g_sQ[12*64];
// conv weights as B-fragment words: [lk][half][tap][cipair 16][72 (64 used)]
__device__ uint32_t g_wBh[10*2*9*16*72];
__device__ uint32_t g_wBl[10*2*9*16*72];

__device__ __forceinline__ float lrelu(float v){ return fmaxf(v, 0.01f*v); }

__device__ __forceinline__ float wsum(float v){
  #pragma unroll
  for(int o=16;o>0;o>>=1) v += __shfl_down_sync(0xffffffffu, v, o);
  return v;
}

__device__ __forceinline__ void bf16split2(float v0, float v1, uint32_t& hp, uint32_t& lp){
  asm("cvt.rn.bf16x2.f32 %0, %1, %2;" : "=r"(hp) : "f"(v1), "f"(v0));
  float h0 = __uint_as_float(hp<<16);
  float h1 = __uint_as_float(hp & 0xffff0000u);
  float l0 = v0 - h0, l1 = v1 - h1;
  asm("cvt.rn.bf16x2.f32 %0, %1, %2;" : "=r"(lp) : "f"(l1), "f"(l0));
}

#define MMA16816(d, a, b0, b1) \
  asm volatile("mma.sync.aligned.m16n8k16.row.col.f32.bf16.bf16.f32 " \
    "{%0,%1,%2,%3}, {%4,%5,%6,%7}, {%8,%9}, {%0,%1,%2,%3};" \
    : "+f"((d)[0]),"+f"((d)[1]),"+f"((d)[2]),"+f"((d)[3]) \
    : "r"((a)[0]),"r"((a)[1]),"r"((a)[2]),"r"((a)[3]), "r"(b0),"r"(b1))

#define REDADD(p, v) asm volatile("red.global.add.f32 [%0], %1;" :: "l"(p), "f"(v) : "memory")

__device__ __forceinline__ void aff_from_stats(const float* sS, const float* sQ,
                                               const float* gm, const float* bt,
                                               int c, float& a, float& cc){
  float mu = sS[c]*(1.f/(float)NHW);
  float var = sQ[c]*(1.f/(float)NHW) - mu*mu;
  a = gm[c]*rsqrtf(var+EPSV);
  cc = bt[c]-mu*a;
}

// ---------------- small kernels ----------------
__global__ void k_zero(){
  int t = blockIdx.x*512 + threadIdx.x;
  if(t < 768){ g_sS[t]=0.f; g_sQ[t]=0.f; }
  if(t < ND2){ g_accS[t]=0.f; g_accQ[t]=0.f; }
  if(t < CH*LDIM){ g_row[t]=0.f; g_col[t]=0.f; }
}

// merged front kernel: blocks [0,788) stats1d, [788,2468) stats2 (8 segs), [2468,3188) prepB
__global__ void k_front(const float* __restrict__ x1, const float* __restrict__ x2,
                        const float* __restrict__ rw){
  int b = blockIdx.x;
  int tid = threadIdx.x;
  if(b < 788){
    const float* p = x1 + b*LDIM;
    float s=0.f,q=0.f;
    for(int i=tid;i<LDIM;i+=256){ float v=p[i]; s+=v; q+=v*v; }
    __shared__ float ss[8], sq[8];
    s = wsum(s); q = wsum(q);
    int w = tid>>5, ln = tid&31;
    if(ln==0){ ss[w]=s; sq[w]=q; }
    __syncthreads();
    if(tid==0){
      float S=0.f,Q=0.f;
      #pragma unroll
      for(int i=0;i<8;i++){S+=ss[i];Q+=sq[i];}
      float mu=S/(float)LDIM; float var=Q/(float)LDIM-mu*mu;
      g_rs1[b]=rsqrtf(var+EPSV);
    }
  } else if(b < 2468){
    int i = b-788;
    int d = i>>3, seg = i&7;
    const float4* p = (const float4*)(x2 + d*NHW + seg*18432);
    float s=0.f,q=0.f;
    for(int i2=tid;i2<4608;i2+=256){
      float4 v=p[i2];
      s += v.x+v.y+v.z+v.w;
      q += v.x*v.x+v.y*v.y+v.z*v.z+v.w*v.w;
    }
    __shared__ float ss2[8], sq2[8];
    s=wsum(s); q=wsum(q);
    int w=tid>>5, ln=tid&31;
    if(ln==0){ ss2[w]=s; sq2[w]=q; }
    __syncthreads();
    if(tid==0){
      float S=0.f,Q=0.f;
      #pragma unroll
      for(int i2=0;i2<8;i2++){S+=ss2[i2];Q+=sq2[i2];}
      atomicAdd(&g_accS[d],S); atomicAdd(&g_accQ[d],Q);
    }
  } else {
    int idx = (b-2468)*256 + tid;
    if(idx >= 10*2*9*16*64) return;
    int n   = idx & 63;
    int cp  = (idx>>6) & 15;
    int tap = (idx>>10) % 9;
    int rest= (idx>>10) / 9;
    int half= rest & 1;
    int lk  = rest >> 1;
    int ci0 = half*32 + cp*2;
    float w0 = rw[((lk*CH + n)*CH + ci0  )*9 + tap];
    float w1 = rw[((lk*CH + n)*CH + ci0+1)*9 + tap];
    uint32_t hp, lp;
    bf16split2(w0, w1, hp, lp);
    int o = ((rest*9 + tap)*16 + cp)*72 + n;
    g_wBh[o] = hp; g_wBl[o] = lp;
  }
}

// merged weight fold (rs2 computed inline from accumulated stats)
__global__ void k_fold(const float* __restrict__ W1, const float* __restrict__ W2){
  int idx = blockIdx.x*256+threadIdx.x;
  if(idx < CH*ND1){
    int c = idx/ND1, d = idx%ND1;
    float rs = g_rs1[d];
    g_W1af[idx] = W1[c*2*ND1 + d]*rs;
    g_W1bf[idx] = W1[c*2*ND1 + ND1 + d]*rs;
  } else {
    int i2 = idx - CH*ND1;
    if(i2 < CH*ND2){
      int d = i2%ND2;
      float mu = g_accS[d]*(1.f/(float)NHW);
      float var = g_accQ[d]*(1.f/(float)NHW) - mu*mu;
      g_W2f[i2] = W2[i2]*rsqrtf(var+EPSV);
    }
  }
}

// rowcol: grid (16 cgroups x 32 segs), 384 threads; x1 slice staged in SMEM once,
// reused for 4 channels; atomic combine (32 colliders/address - fine).
__global__ void k_rowcol(const float* __restrict__ x1){
  __shared__ float xs[25*LDIM];   // 38.4 KB
  int cg = blockIdx.x, seg = blockIdx.y, i = threadIdx.x;
  int d0 = seg*25;
  int dn = ND1 - d0; if(dn > 25) dn = 25;
  if(dn <= 0) return;
  for(int k=0;k<dn;k++) xs[k*LDIM + i] = x1[(d0+k)*LDIM + i];
  __syncthreads();
  #pragma unroll
  for(int cc=0;cc<4;cc++){
    int c = cg*4 + cc;
    const float* wa = g_W1af + c*ND1 + d0;
    const float* wb = g_W1bf + c*ND1 + d0;
    float r0=0.f, c0=0.f;
    for(int k=0;k<dn;k++){
      float v = xs[k*LDIM + i];
      r0 += wa[k]*v; c0 += wb[k]*v;
    }
    atomicAdd(&g_row[c*LDIM+i], r0);
    atomicAdd(&g_col[c*LDIM+i], c0);
  }
}

// rc stats -> a1/c1
__global__ void k_rcstats(const float* __restrict__ g1, const float* __restrict__ b1){
  int c = blockIdx.x;
  float sr=0.f,qr=0.f,sc=0.f,qc=0.f;
  for(int i=threadIdx.x;i<LDIM;i+=128){
    float r=g_row[c*LDIM+i], cl=g_col[c*LDIM+i];
    sr+=r; qr+=r*r; sc+=cl; qc+=cl*cl;
  }
  __shared__ float sm4[4][4];
  sr=wsum(sr); qr=wsum(qr); sc=wsum(sc); qc=wsum(qc);
  int w=threadIdx.x>>5, ln=threadIdx.x&31;
  if(ln==0){ sm4[w][0]=sr; sm4[w][1]=qr; sm4[w][2]=sc; sm4[w][3]=qc; }
  __syncthreads();
  if(threadIdx.x==0){
    float Sr=0.f,Qr=0.f,Sc=0.f,Qc=0.f;
    #pragma unroll
    for(int i=0;i<4;i++){Sr+=sm4[i][0];Qr+=sm4[i][1];Sc+=sm4[i][2];Qc+=sm4[i][3];}
    float mr=Sr/(float)LDIM, mc=Sc/(float)LDIM;
    float vr=Qr/(float)LDIM-mr*mr, vc=Qc/(float)LDIM-mc*mc;
    float rs=rsqrtf(vr+vc+EPSV);
    float a=g1[c]*rs;
    g_a1[c]=a; g_c1[c]=b1[c]-(mr+mc)*a;
  }
}

// pair2 GEMM with packed f32x2
__global__ void k_pair2(const float* __restrict__ x2){
  extern __shared__ float sm[];
  float* W2T = sm;            // [d][c] 210*64
  float* xs  = sm + 13440;    // 6*256
  int tid=threadIdx.x;
  for(int i=tid;i<13440;i+=256){ int d=i>>6, c=i&63; W2T[i]=g_W2f[c*ND2+d]; }
  int cg = tid>>7, pxl = tid&127;
  int pix0 = blockIdx.x*256;
  unsigned long long a0[16], a1[16];
  #pragma unroll
  for(int p=0;p<16;p++){ a0[p]=0ULL; a1[p]=0ULL; }
  __syncthreads();
  for(int d0=0; d0<ND2; d0+=6){
    for(int i=tid;i<384;i+=256)
      ((float4*)xs)[i] = ((const float4*)(x2 + (d0 + (i>>6))*NHW + pix0))[i&63];
    __syncthreads();
    #pragma unroll
    for(int dd=0;dd<6;dd++){
      float2 v = *(const float2*)(xs + dd*256 + pxl*2);
      unsigned long long dv0, dv1;
      asm("mov.b64 %0, {%1,%1};" : "=l"(dv0) : "f"(v.x));
      asm("mov.b64 %0, {%1,%1};" : "=l"(dv1) : "f"(v.y));
      const unsigned long long* wp = (const unsigned long long*)(W2T + (d0+dd)*64 + cg*32);
      #pragma unroll
      for(int p=0;p<16;p++){
        unsigned long long w2 = wp[p];
        asm("fma.rn.f32x2 %0, %1, %2, %0;" : "+l"(a0[p]) : "l"(w2), "l"(dv0));
        asm("fma.rn.f32x2 %0, %1, %2, %0;" : "+l"(a1[p]) : "l"(w2), "l"(dv1));
      }
    }
    __syncthreads();
  }
  int P = pix0 + pxl*2;
  #pragma unroll
  for(int p=0;p<16;p++){
    float l0,h0,l1,h1;
    asm("mov.b64 {%0,%1}, %2;" : "=f"(l0), "=f"(h0) : "l"(a0[p]));
    asm("mov.b64 {%0,%1}, %2;" : "=f"(l1), "=f"(h1) : "l"(a1[p]));
    int c = cg*32 + 2*p;
    g_bufU[c*NHW + P]       = l0;
    g_bufU[c*NHW + P + 1]   = l1;
    g_bufU[(c+1)*NHW + P]   = h0;
    g_bufU[(c+1)*NHW + P+1] = h1;
  }
}

// per-channel sum/sumsq accumulate into a stat set (float4, 16 segs)
__global__ void k_cstats(const float* __restrict__ buf, float* __restrict__ sS, float* __restrict__ sQ){
  int c=blockIdx.x, seg=blockIdx.y;
  const float4* p = (const float4*)(buf + c*NHW + seg*9216);
  float s=0.f,q=0.f;
  for(int i=threadIdx.x;i<2304;i+=256){
    float4 v=p[i];
    s += v.x+v.y+v.z+v.w;
    q += v.x*v.x+v.y*v.y+v.z*v.z+v.w*v.w;
  }
  __shared__ float ss[8], sq[8];
  s=wsum(s); q=wsum(q);
  int w=threadIdx.x>>5, ln=threadIdx.x&31;
  if(ln==0){ ss[w]=s; sq[w]=q; }
  __syncthreads();
  if(threadIdx.x==0){
    float S=0.f,Q=0.f;
    #pragma unroll
    for(int i=0;i<8;i++){S+=ss[i];Q+=sq[i];}
    atomicAdd(&sS[c],S); atomicAdd(&sQ[c],Q);
  }
}

// pair stage, f32x2 (a2/c2 computed inline from stat set 0)
__global__ void k_pair(const float* __restrict__ W3,
                       const float* __restrict__ g2, const float* __restrict__ b2){
  extern __shared__ float sm[];
  float* WaT = sm;             // [d][c] stride 66
  float* WbT = sm + 64*66;
  float* p1s = sm + 2*64*66;
  float* p2s = p1s + 4096;
  float* aS2 = p2s + 4096;     // 64
  float* cS2 = aS2 + 64;       // 64
  int tid=threadIdx.x;
  for(int i=tid;i<4096;i+=256){
    int d=i&63, c=i>>6;
    WaT[d*66+c]=W3[c*128+d];
    WbT[d*66+c]=W3[c*128+64+d];
  }
  if(tid<64){ float a,cc; aff_from_stats(g_sS, g_sQ, g2, b2, tid, a, cc); aS2[tid]=a; cS2[tid]=cc; }
  __syncthreads();
  int P0 = blockIdx.x*64;
  int i0 = P0/LDIM, j0 = P0 - i0*LDIM;
  for(int idx=tid;idx<4096;idx+=256){
    int c=idx>>6, px=idx&63;
    float v1 = g_row[c*LDIM+i0] + g_col[c*LDIM+j0+px];
    p1s[idx] = lrelu(g_a1[c]*v1 + g_c1[c]);
    float u = g_bufU[c*NHW + P0 + px];
    p2s[idx] = lrelu(aS2[c]*u + cS2[c]);
  }
  __syncthreads();
  int pi=tid&31, cg=tid>>5;
  unsigned long long acc[8];
  #pragma unroll
  for(int p=0;p<8;p++) acc[p]=0ULL;
  for(int dd=0;dd<64;dd++){
    float2 v1 = *(const float2*)(p1s + dd*64 + pi*2);
    float2 v2 = *(const float2*)(p2s + dd*64 + pi*2);
    unsigned long long s10,s11,s20,s21;
    asm("mov.b64 %0, {%1,%1};" : "=l"(s10) : "f"(v1.x));
    asm("mov.b64 %0, {%1,%1};" : "=l"(s11) : "f"(v1.y));
    asm("mov.b64 %0, {%1,%1};" : "=l"(s20) : "f"(v2.x));
    asm("mov.b64 %0, {%1,%1};" : "=l"(s21) : "f"(v2.y));
    const unsigned long long* wa = (const unsigned long long*)(WaT + dd*66 + cg*8);
    const unsigned long long* wb = (const unsigned long long*)(WbT + dd*66 + cg*8);
    #pragma unroll
    for(int p=0;p<4;p++){
      unsigned long long wA=wa[p], wB=wb[p];
      asm("fma.rn.f32x2 %0, %1, %2, %0;" : "+l"(acc[p*2  ]) : "l"(wA), "l"(s10));
      asm("fma.rn.f32x2 %0, %1, %2, %0;" : "+l"(acc[p*2  ]) : "l"(wB), "l"(s20));
      asm("fma.rn.f32x2 %0, %1, %2, %0;" : "+l"(acc[p*2+1]) : "l"(wA), "l"(s11));
      asm("fma.rn.f32x2 %0, %1, %2, %0;" : "+l"(acc[p*2+1]) : "l"(wB), "l"(s21));
    }
  }
  #pragma unroll
  for(int p=0;p<4;p++){
    #pragma unroll
    for(int q=0;q<2;q++){
      float lo,hi;
      asm("mov.b64 {%0,%1}, %2;" : "=f"(lo), "=f"(hi) : "l"(acc[p*2+q]));
      int c = cg*8 + 2*p;
      int P = P0 + pi*2 + q;
      g_bufX[c*NHW + P]     = lo;
      g_bufX[(c+1)*NHW + P] = hi;
    }
  }
}

__global__ void k_apply_res(const float* __restrict__ u, const float* __restrict__ res,
                            float* __restrict__ o,
                            const float* __restrict__ sS, const float* __restrict__ sQ,
                            const float* __restrict__ gm, const float* __restrict__ bt){
  int c=blockIdx.y;
  float a,cc; aff_from_stats(sS,sQ,gm,bt,c,a,cc);
  int idx = blockIdx.x*128 + threadIdx.x;
  float4 uv = ((const float4*)(u + c*NHW))[idx];
  float4 rv = ((const float4*)(res + c*NHW))[idx];
  float4 ov;
  ov.x = lrelu(a*uv.x+cc)+rv.x; ov.y = lrelu(a*uv.y+cc)+rv.y;
  ov.z = lrelu(a*uv.z+cc)+rv.z; ov.w = lrelu(a*uv.w+cc)+rv.w;
  ((float4*)(o + c*NHW))[idx] = ov;
}

// ---------------- conv 3x3 dilated 64->64 via mma.sync bf16 hi/lo split ----------------
// 256 threads, 8 warps, occ 2. Fused per-channel stat accumulation in epilogue.
template<int D>
__global__ void __launch_bounds__(256,2)
k_convM(const float* __restrict__ in, float* __restrict__ out,
        const uint32_t* __restrict__ wBh, const uint32_t* __restrict__ wBl,
        const float* __restrict__ sSi, const float* __restrict__ sQi,
        const float* __restrict__ gm,  const float* __restrict__ bt,
        float* __restrict__ sSo, float* __restrict__ sQo,
        const float* __restrict__ resIn, float* __restrict__ resOut){
  constexpr int TW2  = 16+2*D;
  constexpr int PLHW = (D==1)?328:((D==2)?424:584);
  constexpr int TILE_W = 16*PLHW;
  extern __shared__ uint32_t smu[];
  uint32_t* tileH = smu;
  uint32_t* tileL = smu + TILE_W;
  uint32_t* Bh    = smu + 2*TILE_W;     // 2 x 1152
  uint32_t* Bl    = Bh + 2*1152;        // 2 x 1152
  float* aS = (float*)(Bl + 2*1152);    // 64
  float* cS = aS + 64;                  // 64
  float* red = cS + 64;                 // 512

  int tid = threadIdx.x;
  int lane = tid & 31, wid = tid >> 5;
  int wm = wid >> 1, wn = wid & 1;
  int g = lane >> 2, tig = lane & 3;
  int x0 = blockIdx.x*16, y0 = blockIdx.y*16;

  bool doAct = (gm != nullptr);
  bool hasRes = (resIn != nullptr);
  bool wAct = (resOut != nullptr);
  if(tid < 64){
    if(doAct){ float a,cc; aff_from_stats(sSi,sQi,gm,bt,tid,a,cc); aS[tid]=a; cS[tid]=cc; }
    else { aS[tid]=1.f; cS[tid]=0.f; }
  }

  float acc[4][4][4];
  #pragma unroll
  for(int j=0;j<4;j++)
    #pragma unroll
    for(int na=0;na<4;na++)
      #pragma unroll
      for(int q=0;q<4;q++) acc[j][na][q]=0.f;

  for(int half=0; half<2; half++){
    __syncthreads();
    for(int idx=tid; idx<16*TW2*TW2; idx+=256){
      int cp = idx/(TW2*TW2); int rr = idx - cp*(TW2*TW2);
      int r = rr/TW2, c2 = rr - r*TW2;
      int gy = y0 - D + r, gx = x0 - D + c2;
      float v0=0.f, v1=0.f;
      if(((unsigned)gy<384u) && ((unsigned)gx<384u)){
        int ci0 = half*32 + cp*2;
        int off0 = ci0*NHW + gy*LDIM + gx;
        float u0 = in[off0], u1 = in[off0+NHW];
        if(hasRes){
          float t0 = aS[ci0]*u0 + cS[ci0];
          float t1 = aS[ci0+1]*u1 + cS[ci0+1];
          v0 = fmaxf(t0, 0.01f*t0) + resIn[off0];
          v1 = fmaxf(t1, 0.01f*t1) + resIn[off0+NHW];
          if((unsigned)(gy-y0)<16u && (unsigned)(gx-x0)<16u){
            resOut[off0] = v0; resOut[off0+NHW] = v1;
          }
        } else if(doAct){
          float t0 = aS[ci0]*u0 + cS[ci0];     v0 = fmaxf(t0, 0.01f*t0);
          float t1 = aS[ci0+1]*u1 + cS[ci0+1]; v1 = fmaxf(t1, 0.01f*t1);
          if(wAct && (unsigned)(gy-y0)<16u && (unsigned)(gx-x0)<16u){
            resOut[off0] = v0; resOut[off0+NHW] = v1;
          }
        } else { v0=u0; v1=u1; }
      }
      uint32_t hp, lp;
      bf16split2(v0, v1, hp, lp);
      int off = cp*PLHW + r*TW2 + c2;
      tileH[off] = hp; tileL[off] = lp;
    }
    const uint4* bsrcH = (const uint4*)(wBh + (half*9)*1152);
    const uint4* bsrcL = (const uint4*)(wBl + (half*9)*1152);
    for(int i=tid;i<288;i+=256){ ((uint4*)Bh)[i]=bsrcH[i]; ((uint4*)Bl)[i]=bsrcL[i]; }
    __syncthreads();

    for(int tap=0; tap<9; tap++){
      int buf = tap & 1;
      if(tap < 8){
        const uint4* nh = bsrcH + (tap+1)*288;
        const uint4* nl = bsrcL + (tap+1)*288;
        uint4* dh = (uint4*)(Bh + (buf^1)*1152);
        uint4* dl = (uint4*)(Bl + (buf^1)*1152);
        for(int i=tid;i<288;i+=256){ dh[i]=nh[i]; dl[i]=nl[i]; }
      }
      int ky = tap/3, kx = tap - ky*3;
      #pragma unroll
      for(int kc=0;kc<2;kc++){
        uint32_t AH[4][4], AL[4][4];
        const uint32_t* tb = tileH + (kc*8+tig)*PLHW + (ky*D)*TW2 + kx*D + g;
        #pragma unroll
        for(int j=0;j<4;j++){
          const uint32_t* th = tb + (wm*4+j)*TW2;
          AH[j][0]=th[0]; AH[j][1]=th[8]; AH[j][2]=th[4*PLHW]; AH[j][3]=th[4*PLHW+8];
          const uint32_t* tl = th + TILE_W;
          AL[j][0]=tl[0]; AL[j][1]=tl[8]; AL[j][2]=tl[4*PLHW]; AL[j][3]=tl[4*PLHW+8];
        }
        const uint32_t* bbh = Bh + buf*1152 + (kc*8+tig)*72 + wn*32 + g;
        const uint32_t* bbl = Bl + buf*1152 + (kc*8+tig)*72 + wn*32 + g;
        #pragma unroll
        for(int na=0;na<4;na++){
          uint32_t bh0 = bbh[na*8], bh1 = bbh[na*8 + 4*72];
          uint32_t bl0 = bbl[na*8], bl1 = bbl[na*8 + 4*72];
          #pragma unroll
          for(int j=0;j<4;j++) MMA16816(acc[j][na], AH[j], bh0, bh1);
          #pragma unroll
          for(int j=0;j<4;j++) MMA16816(acc[j][na], AH[j], bl0, bl1);
          #pragma unroll
          for(int j=0;j<4;j++) MMA16816(acc[j][na], AL[j], bh0, bh1);
        }
      }
      __syncthreads();
    }
  }
  // epilogue: write output
  #pragma unroll
  for(int j=0;j<4;j++){
    int gy = y0 + wm*4 + j;
    #pragma unroll
    for(int na=0;na<4;na++){
      int co = wn*32 + na*8 + tig*2;
      float* op = out + co*NHW + gy*LDIM + x0;
      op[g]         = acc[j][na][0];
      op[NHW + g]   = acc[j][na][1];
      op[g+8]       = acc[j][na][2];
      op[NHW + g+8] = acc[j][na][3];
    }
  }
  // fused per-channel stats
  float sv[16];
  #pragma unroll
  for(int na=0;na<4;na++){
    #pragma unroll
    for(int par=0;par<2;par++){
      float s=0.f, q=0.f;
      #pragma unroll
      for(int j=0;j<4;j++){
        float v0=acc[j][na][par], v1=acc[j][na][par+2];
        s += v0+v1; q += v0*v0+v1*v1;
      }
      sv[(na*2+par)*2]   = s;
      sv[(na*2+par)*2+1] = q;
    }
  }
  #pragma unroll
  for(int off=4; off<32; off<<=1){
    #pragma unroll
    for(int i=0;i<16;i++) sv[i] += __shfl_xor_sync(0xffffffffu, sv[i], off);
  }
  if(lane<4){
    #pragma unroll
    for(int i=0;i<16;i++) red[wid*64 + lane*16 + i] = sv[i];
  }
  __syncthreads();
  if(tid<128){
    int sq = tid>>6, ch = tid&63;
    int wn_=ch>>5, na_=(ch>>3)&3, tg=(ch>>1)&3, par=ch&1;
    float tot=0.f;
    #pragma unroll
    for(int k=0;k<4;k++) tot += red[(2*k+wn_)*64 + tg*16 + (na_*2+par)*2 + sq];
    REDADD((sq? sQo : sSo)+ch, tot);
  }
}

// ---------------- host ----------------
static void launch_conv(int d, const float* in, float* out,
                        const uint32_t* wh, const uint32_t* wl,
                        const float* sSi, const float* sQi,
                        const float* gm, const float* bt,
                        float* sSo, float* sQo,
                        const float* resIn, float* resOut){
  dim3 g(24,24);
  if(d==1)      k_convM<1><<<g,256,62976>>>(in,out,wh,wl,sSi,sQi,gm,bt,sSo,sQo,resIn,resOut);
  else if(d==2) k_convM<2><<<g,256,75264>>>(in,out,wh,wl,sSi,sQi,gm,bt,sSo,sQo,resIn,resOut);
  else          k_convM<4><<<g,256,95744>>>(in,out,wh,wl,sSi,sQi,gm,bt,sSo,sQo,resIn,resOut);
}

extern "C" void kernel_launch(void* const* d_in, const int* in_sizes, int n_in,
                              void* d_out, int out_size){
  const float* x1 =(const float*)d_in[0];
  const float* x2 =(const float*)d_in[1];
  const float* W1 =(const float*)d_in[2];
  const float* g1 =(const float*)d_in[3];
  const float* b1 =(const float*)d_in[4];
  const float* W2 =(const float*)d_in[5];
  const float* g2 =(const float*)d_in[6];
  const float* b2 =(const float*)d_in[7];
  const float* W3 =(const float*)d_in[8];
  const float* g3 =(const float*)d_in[9];
  const float* b3 =(const float*)d_in[10];
  const float* rw =(const float*)d_in[11];
  const float* rg =(const float*)d_in[13];
  const float* rbe=(const float*)d_in[14];
  float* outp=(float*)d_out;

  float *bufT,*bufU,*bufX,*bufV,*sS,*sQ;
  uint32_t *wBh,*wBl;
  cudaGetSymbolAddress((void**)&bufT, g_bufT);
  cudaGetSymbolAddress((void**)&bufU, g_bufU);
  cudaGetSymbolAddress((void**)&bufX, g_bufX);
  cudaGetSymbolAddress((void**)&bufV, g_bufV);
  cudaGetSymbolAddress((void**)&wBh,  g_wBh);
  cudaGetSymbolAddress((void**)&wBl,  g_wBl);
  cudaGetSymbolAddress((void**)&sS,   g_sS);
  cudaGetSymbolAddress((void**)&sQ,   g_sQ);

  cudaFuncSetAttribute(k_convM<1>, cudaFuncAttributeMaxDynamicSharedMemorySize, 62976);
  cudaFuncSetAttribute(k_convM<2>, cudaFuncAttributeMaxDynamicSharedMemorySize, 75264);
  cudaFuncSetAttribute(k_convM<4>, cudaFuncAttributeMaxDynamicSharedMemorySize, 95744);
  cudaFuncSetAttribute(k_pair2,    cudaFuncAttributeMaxDynamicSharedMemorySize, 61440);
  cudaFuncSetAttribute(k_pair,     cudaFuncAttributeMaxDynamicSharedMemorySize, 67584);

  k_zero<<<48,512>>>();
  k_front<<<3188,256>>>(x1, x2, rw);
  k_fold<<<(CH*ND1+CH*ND2+255)/256,256>>>(W1, W2);
  k_rowcol<<<dim3(16,32),384>>>(x1);
  k_pair2<<<576,256,61440>>>(x2);
  k_rcstats<<<64,128>>>(g1,b1);                                // fills pair2 tail wave
  k_cstats<<<dim3(64,16),256>>>(bufU, sS+0*64, sQ+0*64);      // set 0: pair2 out
  k_pair<<<2304,256,67584>>>(W3, g2, b2);                      // uses set 0
  k_cstats<<<dim3(64,16),256>>>(bufX, sS+1*64, sQ+1*64);      // set 1: pair out (raw)

  const int dil[5]={1,2,4,2,1};
  float* resBuf[2] = {bufV, bufX};
  int cur = 0;   // bufV will hold the activated pair output (residual) after conv1-l0
  for(int l=0;l<5;l++){
    int d=dil[l];
    const uint32_t* wh0 = wBh + (l*2  )*20736;
    const uint32_t* wl0 = wBl + (l*2  )*20736;
    const uint32_t* wh1 = wBh + (l*2+1)*20736;
    const uint32_t* wl1 = wBl + (l*2+1)*20736;
    float* s0S = sS + (2+2*l)*64;  float* s0Q = sQ + (2+2*l)*64;
    float* s1S = sS + (3+2*l)*64;  float* s1Q = sQ + (3+2*l)*64;
    if(l==0){
      launch_conv(d, bufX, bufT, wh0, wl0,
                  sS+1*64, sQ+1*64, g3, b3, s0S, s0Q, nullptr, bufV);
    } else {
      float* sPS = sS + (1+2*l)*64;  float* sPQ = sQ + (1+2*l)*64;
      launch_conv(d, bufU, bufT, wh0, wl0,
                  sPS, sPQ, rg+(2*l-1)*CH, rbe+(2*l-1)*CH, s0S, s0Q,
                  resBuf[cur], resBuf[cur^1]);
      cur ^= 1;
    }
    launch_conv(d, bufT, bufU, wh1, wl1,
                s0S, s0Q, rg+(2*l)*CH, rbe+(2*l)*CH, s1S, s1Q, nullptr,nullptr);
  }
  k_apply_res<<<dim3(288,64),128>>>(bufU, resBuf[cur], outp,
                                    sS+11*64, sQ+11*64, rg+9*CH, rbe+9*CH);
}